// round 11
// baseline (speedup 1.0000x reference)
#include <cuda_runtime.h>
#include <math_constants.h>
#include <cstdint>

// Problem constants
#define S_LEN 1024
#define B_SZ  8
#define H_DIM 1024
#define NHEAD 16
#define HDIM  64
#define M_ROWS (B_SZ * S_LEN)   // 8192

// Scratch for projected Q/K/V, [B*S, H] with m = b*S_LEN + s.
__device__ float g_QL[(size_t)M_ROWS * H_DIM];
__device__ float g_KL[(size_t)M_ROWS * H_DIM];
__device__ float g_VL[(size_t)M_ROWS * H_DIM];

// ---------------------------------------------------------------------------
// Packed fp32x2 helpers
// ---------------------------------------------------------------------------
__device__ __forceinline__ unsigned long long ffma2(
    unsigned long long a, unsigned long long b, unsigned long long c)
{
    unsigned long long d;
    asm("fma.rn.f32x2 %0, %1, %2, %3;" : "=l"(d) : "l"(a), "l"(b), "l"(c));
    return d;
}
__device__ __forceinline__ unsigned long long pack2(float x)
{
    unsigned long long d;
    asm("mov.b64 %0, {%1, %1};" : "=l"(d) : "f"(x));
    return d;
}
__device__ __forceinline__ void unpack2(unsigned long long v, float& lo, float& hi)
{
    asm("mov.b64 {%0, %1}, %2;" : "=f"(lo), "=f"(hi) : "l"(v));
}

// Load 8 duplicated (v,v) pairs from smem as 4x LDS.128 into aa[8].
#define LOAD_AA_DUP(aa, ptr) do { \
    const uint4* _sp = reinterpret_cast<const uint4*>(ptr); \
    uint4* _ap = reinterpret_cast<uint4*>(aa); \
    _ap[0] = _sp[0]; _ap[1] = _sp[1]; _ap[2] = _sp[2]; _ap[3] = _sp[3]; \
} while (0)

// ---------------------------------------------------------------------------
// Merged projection GEMM: Y[m][n] = sum_k X'[m][k]*W[n][k] + b[n]
//   128x128 tile, BK=16, 256 threads, 8x8 per thread, f32x2 inner loop.
//   A stored DUPLICATED in smem ((v,v) pairs) so the inner loop needs no
//   pack2 MOVs. grid = (8, 64, 3).
// ---------------------------------------------------------------------------
__global__ __launch_bounds__(256, 2) void proj_kernel(
    const float* __restrict__ Xq, const float* __restrict__ Xk,
    const float* __restrict__ Xv,
    const float* __restrict__ Wq, const float* __restrict__ bq,
    const float* __restrict__ Wk, const float* __restrict__ bk,
    const float* __restrict__ Wv, const float* __restrict__ bv)
{
    const int z = blockIdx.z;
    const float* X    = (z == 0) ? Xq : ((z == 1) ? Xk : Xv);
    const float* W    = (z == 0) ? Wq : ((z == 1) ? Wk : Wv);
    const float* bias = (z == 0) ? bq : ((z == 1) ? bk : bv);
    float* out        = (z == 0) ? g_QL : ((z == 1) ? g_KL : g_VL);

    const int BK = 16;
    __shared__ float As[BK][268];   // duplicated: [k][m*2 + {0,1}]
    __shared__ float Bs[BK][132];

    const int m0 = blockIdx.y * 128;
    const int n0 = blockIdx.x * 128;
    const int tid = threadIdx.x;
    const int tx = tid & 15;
    const int ty = tid >> 4;

    unsigned long long acc[8][4];
    #pragma unroll
    for (int i = 0; i < 8; i++)
        #pragma unroll
        for (int j = 0; j < 4; j++) acc[i][j] = 0ull;

    for (int k0 = 0; k0 < H_DIM; k0 += BK) {
        #pragma unroll
        for (int l = 0; l < 2; l++) {
            int f  = l * 256 + tid;
            int r  = f >> 2;
            int c4 = f & 3;
            int m  = m0 + r;
            int b  = m >> 10;
            int s  = m & 1023;
            const float4 v = *reinterpret_cast<const float4*>(
                X + ((size_t)(s * B_SZ + b)) * H_DIM + k0 + c4 * 4);
            *reinterpret_cast<float2*>(&As[c4 * 4 + 0][r * 2]) = make_float2(v.x, v.x);
            *reinterpret_cast<float2*>(&As[c4 * 4 + 1][r * 2]) = make_float2(v.y, v.y);
            *reinterpret_cast<float2*>(&As[c4 * 4 + 2][r * 2]) = make_float2(v.z, v.z);
            *reinterpret_cast<float2*>(&As[c4 * 4 + 3][r * 2]) = make_float2(v.w, v.w);
        }
        #pragma unroll
        for (int l = 0; l < 2; l++) {
            int f  = l * 256 + tid;
            int r  = f >> 2;
            int c4 = f & 3;
            const float4 v = *reinterpret_cast<const float4*>(
                W + (size_t)(n0 + r) * H_DIM + k0 + c4 * 4);
            Bs[c4 * 4 + 0][r] = v.x; Bs[c4 * 4 + 1][r] = v.y;
            Bs[c4 * 4 + 2][r] = v.z; Bs[c4 * 4 + 3][r] = v.w;
        }
        __syncthreads();

        #pragma unroll
        for (int kk = 0; kk < BK; kk++) {
            unsigned long long aa[8];
            LOAD_AA_DUP(aa, &As[kk][ty * 16]);
            const unsigned long long* bp =
                reinterpret_cast<const unsigned long long*>(&Bs[kk][tx * 8]);
            unsigned long long b0 = bp[0], b1 = bp[1], b2 = bp[2], b3 = bp[3];
            #pragma unroll
            for (int i = 0; i < 8; i++) {
                acc[i][0] = ffma2(aa[i], b0, acc[i][0]);
                acc[i][1] = ffma2(aa[i], b1, acc[i][1]);
                acc[i][2] = ffma2(aa[i], b2, acc[i][2]);
                acc[i][3] = ffma2(aa[i], b3, acc[i][3]);
            }
        }
        __syncthreads();
    }

    const float4 bsv0 = *reinterpret_cast<const float4*>(bias + n0 + tx * 8);
    const float4 bsv1 = *reinterpret_cast<const float4*>(bias + n0 + tx * 8 + 4);
    #pragma unroll
    for (int i = 0; i < 8; i++) {
        int m = m0 + ty * 8 + i;
        float lo, hi;
        float4 o0, o1;
        unpack2(acc[i][0], lo, hi); o0.x = lo + bsv0.x; o0.y = hi + bsv0.y;
        unpack2(acc[i][1], lo, hi); o0.z = lo + bsv0.z; o0.w = hi + bsv0.w;
        unpack2(acc[i][2], lo, hi); o1.x = lo + bsv1.x; o1.y = hi + bsv1.y;
        unpack2(acc[i][3], lo, hi); o1.z = lo + bsv1.z; o1.w = hi + bsv1.w;
        float* op = out + (size_t)m * H_DIM + n0 + tx * 8;
        *reinterpret_cast<float4*>(op)     = o0;
        *reinterpret_cast<float4*>(op + 4) = o1;
    }
}

// ---------------------------------------------------------------------------
// Fused attention (R5 structure; A-side smem duplicated to kill pack2 MOVs):
//   Phase 1: S = QK^T/8 + mask -> raw to W, online row max/sum.
//   Phase 2: normalize in place (final attn_weights) + P*V -> ctx.
// ---------------------------------------------------------------------------
__global__ __launch_bounds__(256, 2) void attn_kernel(
    const int* __restrict__ mask, float* w, float* out_ctx)
{
    const int bh = blockIdx.y;
    const int b = bh >> 4;
    const int h = bh & 15;
    const int q0 = blockIdx.x * 128;
    const float* Qb = g_QL + (size_t)b * S_LEN * H_DIM + h * HDIM;
    const float* Kb = g_KL + (size_t)b * S_LEN * H_DIM + h * HDIM;
    const float* Vb = g_VL + (size_t)b * S_LEN * H_DIM + h * HDIM;
    float* W = w + (size_t)bh * S_LEN * S_LEN;

    __shared__ float As[16][268];   // duplicated: [k][m*2 + {0,1}]
    __shared__ float Bs[16][132];
    __shared__ float sm_m[128];
    __shared__ float sm_il[128];

    const int tid = threadIdx.x;
    const int tx = tid & 15;
    const int ty = tid >> 4;

    float row_m[8], row_l[8];
    #pragma unroll
    for (int i = 0; i < 8; i++) { row_m[i] = -CUDART_INF_F; row_l[i] = 0.0f; }

    // ---------------- Phase 1: scores + online stats ----------------
    for (int kt = 0; kt < 8; kt++) {
        const int n0 = kt * 128;

        unsigned long long acc[8][4];
        #pragma unroll
        for (int i = 0; i < 8; i++)
            #pragma unroll
            for (int j = 0; j < 4; j++) acc[i][j] = 0ull;

        for (int k0 = 0; k0 < HDIM; k0 += 16) {
            #pragma unroll
            for (int l = 0; l < 2; l++) {
                int f = l * 256 + tid;
                int r = f >> 2, c4 = f & 3;
                const float4 v = *reinterpret_cast<const float4*>(
                    Qb + (size_t)(q0 + r) * H_DIM + k0 + c4 * 4);
                *reinterpret_cast<float2*>(&As[c4 * 4 + 0][r * 2]) = make_float2(v.x, v.x);
                *reinterpret_cast<float2*>(&As[c4 * 4 + 1][r * 2]) = make_float2(v.y, v.y);
                *reinterpret_cast<float2*>(&As[c4 * 4 + 2][r * 2]) = make_float2(v.z, v.z);
                *reinterpret_cast<float2*>(&As[c4 * 4 + 3][r * 2]) = make_float2(v.w, v.w);
            }
            #pragma unroll
            for (int l = 0; l < 2; l++) {
                int f = l * 256 + tid;
                int r = f >> 2, c4 = f & 3;
                const float4 v = *reinterpret_cast<const float4*>(
                    Kb + (size_t)(n0 + r) * H_DIM + k0 + c4 * 4);
                Bs[c4 * 4 + 0][r] = v.x; Bs[c4 * 4 + 1][r] = v.y;
                Bs[c4 * 4 + 2][r] = v.z; Bs[c4 * 4 + 3][r] = v.w;
            }
            __syncthreads();

            #pragma unroll
            for (int kk = 0; kk < 16; kk++) {
                unsigned long long aa[8];
                LOAD_AA_DUP(aa, &As[kk][ty * 16]);
                const unsigned long long* bp =
                    reinterpret_cast<const unsigned long long*>(&Bs[kk][tx * 8]);
                unsigned long long b0 = bp[0], b1 = bp[1], b2 = bp[2], b3 = bp[3];
                #pragma unroll
                for (int i = 0; i < 8; i++) {
                    acc[i][0] = ffma2(aa[i], b0, acc[i][0]);
                    acc[i][1] = ffma2(aa[i], b1, acc[i][1]);
                    acc[i][2] = ffma2(aa[i], b2, acc[i][2]);
                    acc[i][3] = ffma2(aa[i], b3, acc[i][3]);
                }
            }
            __syncthreads();
        }

        float madd[8];
        #pragma unroll
        for (int j = 0; j < 8; j++) {
            int n = n0 + tx * 8 + j;
            madd[j] = (mask[b * S_LEN + n] != 0) ? -1000000.0f : 0.0f;
        }

        float sacc[8][8];
        #pragma unroll
        for (int i = 0; i < 8; i++) {
            #pragma unroll
            for (int jj = 0; jj < 4; jj++) {
                float lo, hi;
                unpack2(acc[i][jj], lo, hi);
                sacc[i][2 * jj]     = lo * 0.125f + madd[2 * jj];
                sacc[i][2 * jj + 1] = hi * 0.125f + madd[2 * jj + 1];
            }
        }

        #pragma unroll
        for (int i = 0; i < 8; i++) {
            float tm = sacc[i][0];
            #pragma unroll
            for (int j = 1; j < 8; j++) tm = fmaxf(tm, sacc[i][j]);
            #pragma unroll
            for (int o = 8; o > 0; o >>= 1)
                tm = fmaxf(tm, __shfl_xor_sync(0xffffffffu, tm, o));
            float ts = 0.0f;
            #pragma unroll
            for (int j = 0; j < 8; j++) ts += __expf(sacc[i][j] - tm);
            #pragma unroll
            for (int o = 8; o > 0; o >>= 1)
                ts += __shfl_xor_sync(0xffffffffu, ts, o);

            float mn = fmaxf(row_m[i], tm);
            row_l[i] = row_l[i] * __expf(row_m[i] - mn) + ts * __expf(tm - mn);
            row_m[i] = mn;

            float4 s0 = make_float4(sacc[i][0], sacc[i][1], sacc[i][2], sacc[i][3]);
            float4 s1 = make_float4(sacc[i][4], sacc[i][5], sacc[i][6], sacc[i][7]);
            float* wp = W + (size_t)(q0 + ty * 8 + i) * S_LEN + n0 + tx * 8;
            *reinterpret_cast<float4*>(wp)     = s0;
            *reinterpret_cast<float4*>(wp + 4) = s1;
        }
    }

    if (tx == 0) {
        #pragma unroll
        for (int i = 0; i < 8; i++) {
            sm_m[ty * 8 + i]  = row_m[i];
            sm_il[ty * 8 + i] = 1.0f / row_l[i];
        }
    }
    __syncthreads();

    // ---------------- Phase 2: normalize + P*V ------
    unsigned long long cacc[8][2];
    #pragma unroll
    for (int i = 0; i < 8; i++) { cacc[i][0] = 0ull; cacc[i][1] = 0ull; }

    for (int k0 = 0; k0 < S_LEN; k0 += 16) {
        #pragma unroll
        for (int l = 0; l < 2; l++) {
            int f = l * 256 + tid;
            int r = f >> 2, c4 = f & 3;
            float* wp = W + (size_t)(q0 + r) * S_LEN + k0 + c4 * 4;
            float4 v = *reinterpret_cast<const float4*>(wp);
            const float mm = sm_m[r];
            const float il = sm_il[r];
            v.x = __expf(v.x - mm) * il;
            v.y = __expf(v.y - mm) * il;
            v.z = __expf(v.z - mm) * il;
            v.w = __expf(v.w - mm) * il;
            *reinterpret_cast<float4*>(wp) = v;
            *reinterpret_cast<float2*>(&As[c4 * 4 + 0][r * 2]) = make_float2(v.x, v.x);
            *reinterpret_cast<float2*>(&As[c4 * 4 + 1][r * 2]) = make_float2(v.y, v.y);
            *reinterpret_cast<float2*>(&As[c4 * 4 + 2][r * 2]) = make_float2(v.z, v.z);
            *reinterpret_cast<float2*>(&As[c4 * 4 + 3][r * 2]) = make_float2(v.w, v.w);
        }
        {
            int r = tid >> 4, c4 = tid & 15;
            const float4 v = *reinterpret_cast<const float4*>(
                Vb + (size_t)(k0 + r) * H_DIM + c4 * 4);
            *reinterpret_cast<float4*>(&Bs[r][c4 * 4]) = v;
        }
        __syncthreads();

        #pragma unroll
        for (int kk = 0; kk < 16; kk++) {
            unsigned long long aa[8];
            LOAD_AA_DUP(aa, &As[kk][ty * 16]);
            const unsigned long long* bp =
                reinterpret_cast<const unsigned long long*>(&Bs[kk][tx * 4]);
            unsigned long long b0 = bp[0], b1 = bp[1];
            #pragma unroll
            for (int i = 0; i < 8; i++) {
                cacc[i][0] = ffma2(aa[i], b0, cacc[i][0]);
                cacc[i][1] = ffma2(aa[i], b1, cacc[i][1]);
            }
        }
        __syncthreads();
    }

    #pragma unroll
    for (int i = 0; i < 8; i++) {
        int s = q0 + ty * 8 + i;
        float lo, hi;
        float4 o;
        unpack2(cacc[i][0], lo, hi); o.x = lo; o.y = hi;
        unpack2(cacc[i][1], lo, hi); o.z = lo; o.w = hi;
        *reinterpret_cast<float4*>(
            out_ctx + ((size_t)s * B_SZ + b) * H_DIM + h * HDIM + tx * 4) = o;
    }
}

// ---------------------------------------------------------------------------
// Launch
// ---------------------------------------------------------------------------
extern "C" void kernel_launch(void* const* d_in, const int* in_sizes, int n_in,
                              void* d_out, int out_size)
{
    const float* q_states = (const float*)d_in[0];
    const float* k_states = (const float*)d_in[1];
    const float* v_states = (const float*)d_in[2];
    const int*   mask     = (const int*)  d_in[3];
    const float* Wq = (const float*)d_in[4];
    const float* bq = (const float*)d_in[5];
    const float* Wk = (const float*)d_in[6];
    const float* bk = (const float*)d_in[7];
    const float* Wv = (const float*)d_in[8];
    const float* bv = (const float*)d_in[9];

    float* out_ctx = (float*)d_out;                           // [S, B, H]
    float* out_w   = out_ctx + (size_t)S_LEN * B_SZ * H_DIM;  // [B, NH, S, S]

    dim3 pg(H_DIM / 128, M_ROWS / 128, 3);   // (8, 64, 3) — one merged launch
    proj_kernel<<<pg, 256>>>(
        q_states, k_states, v_states, Wq, bq, Wk, bk, Wv, bv);

    dim3 ag(S_LEN / 128, B_SZ * NHEAD);      // (8, 128)
    attn_kernel<<<ag, 256>>>(mask, out_w, out_ctx);
}

// round 12
// speedup vs baseline: 1.9995x; 1.9995x over previous
#include <cuda_runtime.h>
#include <math_constants.h>
#include <cstdint>

// Problem constants
#define S_LEN 1024
#define B_SZ  8
#define H_DIM 1024
#define NHEAD 16
#define HDIM  64
#define M_ROWS (B_SZ * S_LEN)   // 8192

// Scratch for projected Q/K/V, [B*S, H] with m = b*S_LEN + s.
__device__ float g_QL[(size_t)M_ROWS * H_DIM];
__device__ float g_KL[(size_t)M_ROWS * H_DIM];
__device__ float g_VL[(size_t)M_ROWS * H_DIM];
// Compacted (unmasked-only) K/V rows, per batch.
__device__ float g_KC[(size_t)M_ROWS * H_DIM];
__device__ float g_VC[(size_t)M_ROWS * H_DIM];
__device__ int g_nb[B_SZ];
__device__ int g_idx[B_SZ][S_LEN];    // compacted j -> dense index
__device__ int g_rank[B_SZ][S_LEN];   // dense n -> # unmasked before n

// ---------------------------------------------------------------------------
// Packed fp32x2 helpers
// ---------------------------------------------------------------------------
__device__ __forceinline__ unsigned long long ffma2(
    unsigned long long a, unsigned long long b, unsigned long long c)
{
    unsigned long long d;
    asm("fma.rn.f32x2 %0, %1, %2, %3;" : "=l"(d) : "l"(a), "l"(b), "l"(c));
    return d;
}
__device__ __forceinline__ unsigned long long pack2(float x)
{
    unsigned long long d;
    asm("mov.b64 %0, {%1, %1};" : "=l"(d) : "f"(x));
    return d;
}
__device__ __forceinline__ void unpack2(unsigned long long v, float& lo, float& hi)
{
    asm("mov.b64 {%0, %1}, %2;" : "=f"(lo), "=f"(hi) : "l"(v));
}

// ---------------------------------------------------------------------------
// Mask compaction: per batch, rank/index arrays via ballot prefix sums.
// grid (B_SZ), block 1024.
// ---------------------------------------------------------------------------
__global__ void compact_kernel(const int* __restrict__ mask)
{
    const int b = blockIdx.x;
    const int tid = threadIdx.x;
    const int lane = tid & 31, wid = tid >> 5;

    int um = (mask[b * S_LEN + tid] == 0) ? 1 : 0;
    unsigned bal = __ballot_sync(0xffffffffu, um);
    int pre = __popc(bal & ((1u << lane) - 1));
    int wcnt = __popc(bal);

    __shared__ int wbase[32];
    __shared__ int wpre[32];
    if (lane == 0) wbase[wid] = wcnt;
    __syncthreads();
    if (wid == 0) {
        int v = wbase[lane];
        int x = v;
        #pragma unroll
        for (int o = 1; o < 32; o <<= 1) {
            int y = __shfl_up_sync(0xffffffffu, x, o);
            if (lane >= o) x += y;
        }
        wpre[lane] = x - v;
        if (lane == 31) g_nb[b] = x;
    }
    __syncthreads();

    int r = wpre[wid] + pre;
    g_rank[b][tid] = r;
    if (um) g_idx[b][r] = tid;
}

// ---------------------------------------------------------------------------
// Gather compacted K/V rows. grid (S_LEN, B_SZ), block 256.
// ---------------------------------------------------------------------------
__global__ void gather_kernel()
{
    const int b = blockIdx.y;
    const int j = blockIdx.x;
    if (j >= g_nb[b]) return;
    const int src = g_idx[b][j];
    const size_t so = ((size_t)b * S_LEN + src) * H_DIM;
    const size_t dof = ((size_t)b * S_LEN + j) * H_DIM;
    const float4* ks = reinterpret_cast<const float4*>(g_KL + so);
    const float4* vs = reinterpret_cast<const float4*>(g_VL + so);
    float4* kd = reinterpret_cast<float4*>(g_KC + dof);
    float4* vd = reinterpret_cast<float4*>(g_VC + dof);
    kd[threadIdx.x] = ks[threadIdx.x];
    vd[threadIdx.x] = vs[threadIdx.x];
}

// ---------------------------------------------------------------------------
// Merged projection GEMM (proven R10 version): 128x128 tile, BK=16,
// 8x8 per thread, f32x2 inner loop. grid = (8, 64, 3).
// ---------------------------------------------------------------------------
__global__ __launch_bounds__(256, 2) void proj_kernel(
    const float* __restrict__ Xq, const float* __restrict__ Xk,
    const float* __restrict__ Xv,
    const float* __restrict__ Wq, const float* __restrict__ bq,
    const float* __restrict__ Wk, const float* __restrict__ bk,
    const float* __restrict__ Wv, const float* __restrict__ bv)
{
    const int z = blockIdx.z;
    const float* X    = (z == 0) ? Xq : ((z == 1) ? Xk : Xv);
    const float* W    = (z == 0) ? Wq : ((z == 1) ? Wk : Wv);
    const float* bias = (z == 0) ? bq : ((z == 1) ? bk : bv);
    float* out        = (z == 0) ? g_QL : ((z == 1) ? g_KL : g_VL);

    const int BK = 16;
    __shared__ float As[BK][132];
    __shared__ float Bs[BK][132];

    const int m0 = blockIdx.y * 128;
    const int n0 = blockIdx.x * 128;
    const int tid = threadIdx.x;
    const int tx = tid & 15;
    const int ty = tid >> 4;

    unsigned long long acc[8][4];
    #pragma unroll
    for (int i = 0; i < 8; i++)
        #pragma unroll
        for (int j = 0; j < 4; j++) acc[i][j] = 0ull;

    for (int k0 = 0; k0 < H_DIM; k0 += BK) {
        #pragma unroll
        for (int l = 0; l < 2; l++) {
            int f  = l * 256 + tid;
            int r  = f >> 2;
            int c4 = f & 3;
            int m  = m0 + r;
            int b  = m >> 10;
            int s  = m & 1023;
            const float4 v = *reinterpret_cast<const float4*>(
                X + ((size_t)(s * B_SZ + b)) * H_DIM + k0 + c4 * 4);
            As[c4 * 4 + 0][r] = v.x; As[c4 * 4 + 1][r] = v.y;
            As[c4 * 4 + 2][r] = v.z; As[c4 * 4 + 3][r] = v.w;
        }
        #pragma unroll
        for (int l = 0; l < 2; l++) {
            int f  = l * 256 + tid;
            int r  = f >> 2;
            int c4 = f & 3;
            const float4 v = *reinterpret_cast<const float4*>(
                W + (size_t)(n0 + r) * H_DIM + k0 + c4 * 4);
            Bs[c4 * 4 + 0][r] = v.x; Bs[c4 * 4 + 1][r] = v.y;
            Bs[c4 * 4 + 2][r] = v.z; Bs[c4 * 4 + 3][r] = v.w;
        }
        __syncthreads();

        #pragma unroll
        for (int kk = 0; kk < BK; kk++) {
            float4 a0 = *reinterpret_cast<const float4*>(&As[kk][ty * 8]);
            float4 a1 = *reinterpret_cast<const float4*>(&As[kk][ty * 8 + 4]);
            unsigned long long aa[8];
            aa[0] = pack2(a0.x); aa[1] = pack2(a0.y); aa[2] = pack2(a0.z); aa[3] = pack2(a0.w);
            aa[4] = pack2(a1.x); aa[5] = pack2(a1.y); aa[6] = pack2(a1.z); aa[7] = pack2(a1.w);
            const unsigned long long* bp =
                reinterpret_cast<const unsigned long long*>(&Bs[kk][tx * 8]);
            unsigned long long b0 = bp[0], b1 = bp[1], b2 = bp[2], b3 = bp[3];
            #pragma unroll
            for (int i = 0; i < 8; i++) {
                acc[i][0] = ffma2(aa[i], b0, acc[i][0]);
                acc[i][1] = ffma2(aa[i], b1, acc[i][1]);
                acc[i][2] = ffma2(aa[i], b2, acc[i][2]);
                acc[i][3] = ffma2(aa[i], b3, acc[i][3]);
            }
        }
        __syncthreads();
    }

    const float4 bsv0 = *reinterpret_cast<const float4*>(bias + n0 + tx * 8);
    const float4 bsv1 = *reinterpret_cast<const float4*>(bias + n0 + tx * 8 + 4);
    #pragma unroll
    for (int i = 0; i < 8; i++) {
        int m = m0 + ty * 8 + i;
        float lo, hi;
        float4 o0, o1;
        unpack2(acc[i][0], lo, hi); o0.x = lo + bsv0.x; o0.y = hi + bsv0.y;
        unpack2(acc[i][1], lo, hi); o0.z = lo + bsv0.z; o0.w = hi + bsv0.w;
        unpack2(acc[i][2], lo, hi); o1.x = lo + bsv1.x; o1.y = hi + bsv1.y;
        unpack2(acc[i][3], lo, hi); o1.z = lo + bsv1.z; o1.w = hi + bsv1.w;
        float* op = out + (size_t)m * H_DIM + n0 + tx * 8;
        *reinterpret_cast<float4*>(op)     = o0;
        *reinterpret_cast<float4*>(op + 4) = o1;
    }
}

// ---------------------------------------------------------------------------
// Fused attention over COMPACTED keys (R10 structure for phases 1-2):
//   Phase 1: S = Q Kc^T/8 over nb compacted cols -> raw compacted into W,
//            online row max/sum. Out-of-range cols forced to -1e6 (weight 0).
//   Phase 2: normalize compacted in place + P*Vc -> ctx.
//   Phase 3: expand compacted normalized weights to dense layout in W,
//            zeros at masked columns (right-to-left, in-place safe since
//            rank(n) <= n).
// ---------------------------------------------------------------------------
__global__ __launch_bounds__(256, 2) void attn_kernel(
    const int* __restrict__ mask, float* w, float* out_ctx)
{
    const int bh = blockIdx.y;
    const int b = bh >> 4;
    const int h = bh & 15;
    const int q0 = blockIdx.x * 128;
    const float* Qb = g_QL + (size_t)b * S_LEN * H_DIM + h * HDIM;
    const float* Kb = g_KC + (size_t)b * S_LEN * H_DIM + h * HDIM;  // compacted
    const float* Vb = g_VC + (size_t)b * S_LEN * H_DIM + h * HDIM;  // compacted
    float* W = w + (size_t)bh * S_LEN * S_LEN;

    __shared__ float As[16][132];
    __shared__ float Bs[16][132];
    __shared__ float sm_m[128];
    __shared__ float sm_il[128];
    __shared__ float smbuf[128][33];
    __shared__ int   sm_rank[S_LEN];
    __shared__ int   sm_um[S_LEN];

    const int tid = threadIdx.x;
    const int tx = tid & 15;
    const int ty = tid >> 4;

    const int nb = g_nb[b];
    const int ktiles = (nb + 127) >> 7;      // 1..8
    const int kc_end = ktiles * 128;

    float row_m[8], row_l[8];
    #pragma unroll
    for (int i = 0; i < 8; i++) { row_m[i] = -CUDART_INF_F; row_l[i] = 0.0f; }

    // ---------------- Phase 1: compacted scores + online stats ------------
    for (int kt = 0; kt < ktiles; kt++) {
        const int n0 = kt * 128;

        unsigned long long acc[8][4];
        #pragma unroll
        for (int i = 0; i < 8; i++)
            #pragma unroll
            for (int j = 0; j < 4; j++) acc[i][j] = 0ull;

        for (int k0 = 0; k0 < HDIM; k0 += 16) {
            #pragma unroll
            for (int l = 0; l < 2; l++) {
                int f = l * 256 + tid;
                int r = f >> 2, c4 = f & 3;
                const float4 v = *reinterpret_cast<const float4*>(
                    Qb + (size_t)(q0 + r) * H_DIM + k0 + c4 * 4);
                As[c4 * 4 + 0][r] = v.x; As[c4 * 4 + 1][r] = v.y;
                As[c4 * 4 + 2][r] = v.z; As[c4 * 4 + 3][r] = v.w;
            }
            #pragma unroll
            for (int l = 0; l < 2; l++) {
                int f = l * 256 + tid;
                int r = f >> 2, c4 = f & 3;
                const float4 v = *reinterpret_cast<const float4*>(
                    Kb + (size_t)(n0 + r) * H_DIM + k0 + c4 * 4);
                Bs[c4 * 4 + 0][r] = v.x; Bs[c4 * 4 + 1][r] = v.y;
                Bs[c4 * 4 + 2][r] = v.z; Bs[c4 * 4 + 3][r] = v.w;
            }
            __syncthreads();

            #pragma unroll
            for (int kk = 0; kk < 16; kk++) {
                float4 a0 = *reinterpret_cast<const float4*>(&As[kk][ty * 8]);
                float4 a1 = *reinterpret_cast<const float4*>(&As[kk][ty * 8 + 4]);
                unsigned long long aa[8];
                aa[0] = pack2(a0.x); aa[1] = pack2(a0.y); aa[2] = pack2(a0.z); aa[3] = pack2(a0.w);
                aa[4] = pack2(a1.x); aa[5] = pack2(a1.y); aa[6] = pack2(a1.z); aa[7] = pack2(a1.w);
                const unsigned long long* bp =
                    reinterpret_cast<const unsigned long long*>(&Bs[kk][tx * 8]);
                unsigned long long b0 = bp[0], b1 = bp[1], b2 = bp[2], b3 = bp[3];
                #pragma unroll
                for (int i = 0; i < 8; i++) {
                    acc[i][0] = ffma2(aa[i], b0, acc[i][0]);
                    acc[i][1] = ffma2(aa[i], b1, acc[i][1]);
                    acc[i][2] = ffma2(aa[i], b2, acc[i][2]);
                    acc[i][3] = ffma2(aa[i], b3, acc[i][3]);
                }
            }
            __syncthreads();
        }

        // out-of-range compacted columns act like masked (-1e6 -> weight 0)
        float madd[8];
        #pragma unroll
        for (int j = 0; j < 8; j++) {
            int cj = n0 + tx * 8 + j;
            madd[j] = (cj < nb) ? 0.0f : -1000000.0f;
        }

        float sacc[8][8];
        #pragma unroll
        for (int i = 0; i < 8; i++) {
            #pragma unroll
            for (int jj = 0; jj < 4; jj++) {
                float lo, hi;
                unpack2(acc[i][jj], lo, hi);
                sacc[i][2 * jj]     = lo * 0.125f + madd[2 * jj];
                sacc[i][2 * jj + 1] = hi * 0.125f + madd[2 * jj + 1];
            }
        }

        #pragma unroll
        for (int i = 0; i < 8; i++) {
            float tm = sacc[i][0];
            #pragma unroll
            for (int j = 1; j < 8; j++) tm = fmaxf(tm, sacc[i][j]);
            #pragma unroll
            for (int o = 8; o > 0; o >>= 1)
                tm = fmaxf(tm, __shfl_xor_sync(0xffffffffu, tm, o));
            float ts = 0.0f;
            #pragma unroll
            for (int j = 0; j < 8; j++) ts += __expf(sacc[i][j] - tm);
            #pragma unroll
            for (int o = 8; o > 0; o >>= 1)
                ts += __shfl_xor_sync(0xffffffffu, ts, o);

            float mn = fmaxf(row_m[i], tm);
            row_l[i] = row_l[i] * __expf(row_m[i] - mn) + ts * __expf(tm - mn);
            row_m[i] = mn;

            float4 s0 = make_float4(sacc[i][0], sacc[i][1], sacc[i][2], sacc[i][3]);
            float4 s1 = make_float4(sacc[i][4], sacc[i][5], sacc[i][6], sacc[i][7]);
            float* wp = W + (size_t)(q0 + ty * 8 + i) * S_LEN + n0 + tx * 8;
            *reinterpret_cast<float4*>(wp)     = s0;
            *reinterpret_cast<float4*>(wp + 4) = s1;
        }
    }

    if (tx == 0) {
        #pragma unroll
        for (int i = 0; i < 8; i++) {
            sm_m[ty * 8 + i]  = row_m[i];
            sm_il[ty * 8 + i] = 1.0f / row_l[i];
        }
    }
    __syncthreads();

    // ---------------- Phase 2: normalize compacted + P*Vc -----------------
    unsigned long long cacc[8][2];
    #pragma unroll
    for (int i = 0; i < 8; i++) { cacc[i][0] = 0ull; cacc[i][1] = 0ull; }

    for (int k0 = 0; k0 < kc_end; k0 += 16) {
        #pragma unroll
        for (int l = 0; l < 2; l++) {
            int f = l * 256 + tid;
            int r = f >> 2, c4 = f & 3;
            float* wp = W + (size_t)(q0 + r) * S_LEN + k0 + c4 * 4;
            float4 v = *reinterpret_cast<const float4*>(wp);
            const float mm = sm_m[r];
            const float il = sm_il[r];
            v.x = __expf(v.x - mm) * il;
            v.y = __expf(v.y - mm) * il;
            v.z = __expf(v.z - mm) * il;
            v.w = __expf(v.w - mm) * il;
            *reinterpret_cast<float4*>(wp) = v;
            As[c4 * 4 + 0][r] = v.x; As[c4 * 4 + 1][r] = v.y;
            As[c4 * 4 + 2][r] = v.z; As[c4 * 4 + 3][r] = v.w;
        }
        {
            int r = tid >> 4, c4 = tid & 15;
            const float4 v = *reinterpret_cast<const float4*>(
                Vb + (size_t)(k0 + r) * H_DIM + c4 * 4);
            *reinterpret_cast<float4*>(&Bs[r][c4 * 4]) = v;
        }
        __syncthreads();

        #pragma unroll
        for (int kk = 0; kk < 16; kk++) {
            float4 a0 = *reinterpret_cast<const float4*>(&As[kk][ty * 8]);
            float4 a1 = *reinterpret_cast<const float4*>(&As[kk][ty * 8 + 4]);
            unsigned long long aa[8];
            aa[0] = pack2(a0.x); aa[1] = pack2(a0.y); aa[2] = pack2(a0.z); aa[3] = pack2(a0.w);
            aa[4] = pack2(a1.x); aa[5] = pack2(a1.y); aa[6] = pack2(a1.z); aa[7] = pack2(a1.w);
            const unsigned long long* bp =
                reinterpret_cast<const unsigned long long*>(&Bs[kk][tx * 4]);
            unsigned long long b0 = bp[0], b1 = bp[1];
            #pragma unroll
            for (int i = 0; i < 8; i++) {
                cacc[i][0] = ffma2(aa[i], b0, cacc[i][0]);
                cacc[i][1] = ffma2(aa[i], b1, cacc[i][1]);
            }
        }
        __syncthreads();
    }

    // write ctx in [S, B, H] layout
    #pragma unroll
    for (int i = 0; i < 8; i++) {
        int s = q0 + ty * 8 + i;
        float lo, hi;
        float4 o;
        unpack2(cacc[i][0], lo, hi); o.x = lo; o.y = hi;
        unpack2(cacc[i][1], lo, hi); o.z = lo; o.w = hi;
        *reinterpret_cast<float4*>(
            out_ctx + ((size_t)s * B_SZ + b) * H_DIM + h * HDIM + tx * 4) = o;
    }

    // ---------------- Phase 3: expand compacted -> dense weights ----------
    for (int n = tid; n < S_LEN; n += 256) {
        sm_rank[n] = g_rank[b][n];
        sm_um[n]   = (mask[b * S_LEN + n] == 0) ? 1 : 0;
    }
    __syncthreads();

    const int row  = tid >> 1;    // 0..127
    const int half = tid & 1;     // 16 dense cols each
    float* wrow = W + (size_t)(q0 + row) * S_LEN;

    for (int s = 31; s >= 0; s--) {
        const int n0 = s * 32;
        const int r0 = sm_rank[n0];
        const int r1 = (n0 + 32 < S_LEN) ? sm_rank[n0 + 32] : nb;
        const int width = r1 - r0;

        // buffer this segment's compacted values (before overwriting)
        for (int i = half; i < width; i += 2)
            smbuf[row][i] = wrow[r0 + i];
        __syncthreads();

        // dense write: unmasked -> buffered value, masked -> 0
        #pragma unroll
        for (int i = 0; i < 4; i++) {
            const int nb4 = n0 + half * 16 + i * 4;
            float4 o;
            o.x = sm_um[nb4 + 0] ? smbuf[row][sm_rank[nb4 + 0] - r0] : 0.0f;
            o.y = sm_um[nb4 + 1] ? smbuf[row][sm_rank[nb4 + 1] - r0] : 0.0f;
            o.z = sm_um[nb4 + 2] ? smbuf[row][sm_rank[nb4 + 2] - r0] : 0.0f;
            o.w = sm_um[nb4 + 3] ? smbuf[row][sm_rank[nb4 + 3] - r0] : 0.0f;
            *reinterpret_cast<float4*>(wrow + nb4) = o;
        }
        __syncthreads();
    }
}

// ---------------------------------------------------------------------------
// Launch
// ---------------------------------------------------------------------------
extern "C" void kernel_launch(void* const* d_in, const int* in_sizes, int n_in,
                              void* d_out, int out_size)
{
    const float* q_states = (const float*)d_in[0];
    const float* k_states = (const float*)d_in[1];
    const float* v_states = (const float*)d_in[2];
    const int*   mask     = (const int*)  d_in[3];
    const float* Wq = (const float*)d_in[4];
    const float* bq = (const float*)d_in[5];
    const float* Wk = (const float*)d_in[6];
    const float* bk = (const float*)d_in[7];
    const float* Wv = (const float*)d_in[8];
    const float* bv = (const float*)d_in[9];

    float* out_ctx = (float*)d_out;                           // [S, B, H]
    float* out_w   = out_ctx + (size_t)S_LEN * B_SZ * H_DIM;  // [B, NH, S, S]

    dim3 pg(H_DIM / 128, M_ROWS / 128, 3);   // (8, 64, 3) — one merged launch
    proj_kernel<<<pg, 256>>>(
        q_states, k_states, v_states, Wq, bq, Wk, bk, Wv, bv);

    compact_kernel<<<B_SZ, 1024>>>(mask);
    gather_kernel<<<dim3(S_LEN, B_SZ), 256>>>();

    dim3 ag(S_LEN / 128, B_SZ * NHEAD);      // (8, 128)
    attn_kernel<<<ag, 256>>>(mask, out_w, out_ctx);
}

// round 13
// speedup vs baseline: 2.5139x; 1.2573x over previous
#include <cuda_runtime.h>
#include <cuda_bf16.h>
#include <math_constants.h>
#include <cstdint>

// Problem constants
#define S_LEN 1024
#define B_SZ  8
#define H_DIM 1024
#define NHEAD 16
#define HDIM  64
#define M_ROWS (B_SZ * S_LEN)   // 8192

// Scratch for projected Q/K/V, [B*S, H] with m = b*S_LEN + s.
__device__ float g_QL[(size_t)M_ROWS * H_DIM];
__device__ float g_KL[(size_t)M_ROWS * H_DIM];
__device__ float g_VL[(size_t)M_ROWS * H_DIM];
// Compacted (unmasked-only) K/V rows, per batch.
__device__ float g_KC[(size_t)M_ROWS * H_DIM];
__device__ float g_VC[(size_t)M_ROWS * H_DIM];
__device__ int g_nb[B_SZ];
__device__ int g_idx[B_SZ][S_LEN];    // compacted j -> dense index
__device__ int g_rank[B_SZ][S_LEN];   // dense n -> # unmasked before n

// Pre-converted bf16 hi/lo operands for the HMMA projection GEMMs.
// X rows stored batch-first: row m = b*S+s. W rows as [n][k].
__device__ __nv_bfloat16 g_XH[3][(size_t)M_ROWS * H_DIM];
__device__ __nv_bfloat16 g_XL[3][(size_t)M_ROWS * H_DIM];
__device__ __nv_bfloat16 g_WH[3][(size_t)H_DIM * H_DIM];
__device__ __nv_bfloat16 g_WL[3][(size_t)H_DIM * H_DIM];

// ---------------------------------------------------------------------------
// Helpers
// ---------------------------------------------------------------------------
__device__ __forceinline__ uint32_t smem_to_u32(const void* p) {
    uint32_t a;
    asm("{ .reg .u64 t; cvta.to.shared.u64 t, %1; cvt.u32.u64 %0, t; }"
        : "=r"(a) : "l"(p));
    return a;
}

// mma.sync m16n8k16 row.col f32.bf16.bf16.f32
__device__ __forceinline__ void mma16816(float* c, const uint32_t* a, const uint32_t* b)
{
    asm volatile(
        "mma.sync.aligned.m16n8k16.row.col.f32.bf16.bf16.f32 "
        "{%0,%1,%2,%3},{%4,%5,%6,%7},{%8,%9},{%0,%1,%2,%3};"
        : "+f"(c[0]), "+f"(c[1]), "+f"(c[2]), "+f"(c[3])
        : "r"(a[0]), "r"(a[1]), "r"(a[2]), "r"(a[3]), "r"(b[0]), "r"(b[1]));
}

__device__ __forceinline__ void ldsm4(uint32_t* r, uint32_t addr)
{
    asm volatile("ldmatrix.sync.aligned.m8n8.x4.shared.b16 {%0,%1,%2,%3},[%4];"
                 : "=r"(r[0]), "=r"(r[1]), "=r"(r[2]), "=r"(r[3]) : "r"(addr));
}

// Packed fp32x2 helpers (attention kernel)
__device__ __forceinline__ unsigned long long ffma2(
    unsigned long long a, unsigned long long b, unsigned long long c)
{
    unsigned long long d;
    asm("fma.rn.f32x2 %0, %1, %2, %3;" : "=l"(d) : "l"(a), "l"(b), "l"(c));
    return d;
}
__device__ __forceinline__ unsigned long long pack2(float x)
{
    unsigned long long d;
    asm("mov.b64 %0, {%1, %1};" : "=l"(d) : "f"(x));
    return d;
}
__device__ __forceinline__ void unpack2(unsigned long long v, float& lo, float& hi)
{
    asm("mov.b64 {%0, %1}, %2;" : "=f"(lo), "=f"(hi) : "l"(v));
}

// fp32 -> bf16 hi/lo split of a float4; outputs packed bf16x2 words.
__device__ __forceinline__ void cvt4_split(
    float4 v, uint32_t& h0, uint32_t& h1, uint32_t& l0, uint32_t& l1)
{
    __nv_bfloat16 hx = __float2bfloat16_rn(v.x);
    __nv_bfloat16 hy = __float2bfloat16_rn(v.y);
    __nv_bfloat16 hz = __float2bfloat16_rn(v.z);
    __nv_bfloat16 hw = __float2bfloat16_rn(v.w);
    h0 = (uint32_t)__bfloat16_as_ushort(hx) | ((uint32_t)__bfloat16_as_ushort(hy) << 16);
    h1 = (uint32_t)__bfloat16_as_ushort(hz) | ((uint32_t)__bfloat16_as_ushort(hw) << 16);
    __nv_bfloat16 lx = __float2bfloat16_rn(v.x - __bfloat162float(hx));
    __nv_bfloat16 ly = __float2bfloat16_rn(v.y - __bfloat162float(hy));
    __nv_bfloat16 lz = __float2bfloat16_rn(v.z - __bfloat162float(hz));
    __nv_bfloat16 lw = __float2bfloat16_rn(v.w - __bfloat162float(hw));
    l0 = (uint32_t)__bfloat16_as_ushort(lx) | ((uint32_t)__bfloat16_as_ushort(ly) << 16);
    l1 = (uint32_t)__bfloat16_as_ushort(lz) | ((uint32_t)__bfloat16_as_ushort(lw) << 16);
}

// ---------------------------------------------------------------------------
// Pre-convert X (seq-first fp32) and W to bf16 hi/lo buffers (done ONCE, so
// the HMMA GEMM staging is a pure copy). One block per row; one float4/thread.
// Rows: z in {0,1,2}; r<8192 -> X row m=r (b=r>>10, s=r&1023); else W row.
// ---------------------------------------------------------------------------
__global__ __launch_bounds__(256) void preconv_kernel(
    const float* __restrict__ Xq, const float* __restrict__ Xk,
    const float* __restrict__ Xv,
    const float* __restrict__ Wq, const float* __restrict__ Wk,
    const float* __restrict__ Wv)
{
    const int row = blockIdx.x;          // 0..27647
    const int z = row / 9216;
    const int r = row % 9216;
    const int col = threadIdx.x * 4;

    const float* src;
    __nv_bfloat16 *dh, *dl;
    if (r < M_ROWS) {
        const float* X = (z == 0) ? Xq : ((z == 1) ? Xk : Xv);
        const int b = r >> 10, s = r & 1023;
        src = X + ((size_t)(s * B_SZ + b)) * H_DIM;
        dh = g_XH[z] + (size_t)r * H_DIM;
        dl = g_XL[z] + (size_t)r * H_DIM;
    } else {
        const int rw = r - M_ROWS;
        const float* W = (z == 0) ? Wq : ((z == 1) ? Wk : Wv);
        src = W + (size_t)rw * H_DIM;
        dh = g_WH[z] + (size_t)rw * H_DIM;
        dl = g_WL[z] + (size_t)rw * H_DIM;
    }

    float4 v = *reinterpret_cast<const float4*>(src + col);
    uint32_t h0, h1, l0, l1;
    cvt4_split(v, h0, h1, l0, l1);
    *reinterpret_cast<uint2*>(dh + col) = make_uint2(h0, h1);
    *reinterpret_cast<uint2*>(dl + col) = make_uint2(l0, l1);
}

// ---------------------------------------------------------------------------
// Projection GEMM via mma.sync (HMMA), split-bf16 3-term compensation.
// Identical mma core / fragment layout to the R8-verified kernel; staging is
// now a pure bf16 copy from the pre-converted buffers.
//   CTA tile 128x128, K-chunk 32, 8 warps as 2(m)x4(n) -> 64x32 warp tiles.
//   grid = (8, 64, 3).
// ---------------------------------------------------------------------------
#define PROW 40   // padded row stride in bf16 elems (80B)

__global__ __launch_bounds__(256) void proj_mma_kernel(
    const float* __restrict__ bq, const float* __restrict__ bk,
    const float* __restrict__ bv)
{
    __shared__ __align__(16) uint16_t sAhi[128 * PROW];
    __shared__ __align__(16) uint16_t sAlo[128 * PROW];
    __shared__ __align__(16) uint16_t sBhi[128 * PROW];
    __shared__ __align__(16) uint16_t sBlo[128 * PROW];

    const int z = blockIdx.z;
    const float* bias = (z == 0) ? bq : ((z == 1) ? bk : bv);
    float* out        = (z == 0) ? g_QL : ((z == 1) ? g_KL : g_VL);

    const int m0 = blockIdx.y * 128;
    const int n0 = blockIdx.x * 128;

    const __nv_bfloat16* Ah = g_XH[z] + (size_t)m0 * H_DIM;
    const __nv_bfloat16* Al = g_XL[z] + (size_t)m0 * H_DIM;
    const __nv_bfloat16* Bh = g_WH[z] + (size_t)n0 * H_DIM;
    const __nv_bfloat16* Bl = g_WL[z] + (size_t)n0 * H_DIM;

    const int tid  = threadIdx.x;
    const int lane = tid & 31;
    const int wid  = tid >> 5;
    const int warp_m = wid & 1;
    const int warp_n = wid >> 1;

    const uint32_t uAhi = smem_to_u32(sAhi);
    const uint32_t uAlo = smem_to_u32(sAlo);
    const uint32_t uBhi = smem_to_u32(sBhi);
    const uint32_t uBlo = smem_to_u32(sBlo);

    float acc[4][4][4];
    #pragma unroll
    for (int i = 0; i < 4; i++)
        #pragma unroll
        for (int j = 0; j < 4; j++)
            #pragma unroll
            for (int k = 0; k < 4; k++) acc[i][j][k] = 0.0f;

    const int sr = tid >> 1;   // staging: 2 threads/row, 16 bf16 each
    const int hf = tid & 1;

    const int a_row = warp_m * 64 + (lane & 15);
    const uint32_t a_colb = (uint32_t)((lane >> 4) << 4);
    const int b_row = warp_n * 32 + (lane & 7) + ((lane & 16) ? 8 : 0);
    const uint32_t b_colb = (uint32_t)((lane & 8) ? 16 : 0);

    for (int c = 0; c < H_DIM / 32; c++) {
        // ---- stage chunk c: pure bf16 copies (uint2 = 4 bf16) ----
        {
            const size_t go = (size_t)sr * H_DIM + c * 32 + hf * 16;
            const int    so = sr * PROW + hf * 16;
            #pragma unroll
            for (int i = 0; i < 4; i++) {
                *reinterpret_cast<uint2*>(&sAhi[so + i * 4]) =
                    *reinterpret_cast<const uint2*>(Ah + go + i * 4);
                *reinterpret_cast<uint2*>(&sAlo[so + i * 4]) =
                    *reinterpret_cast<const uint2*>(Al + go + i * 4);
                *reinterpret_cast<uint2*>(&sBhi[so + i * 4]) =
                    *reinterpret_cast<const uint2*>(Bh + go + i * 4);
                *reinterpret_cast<uint2*>(&sBlo[so + i * 4]) =
                    *reinterpret_cast<const uint2*>(Bl + go + i * 4);
            }
        }
        __syncthreads();

        // ---- mma phase: 2 k16 steps (verbatim R8 core) ----
        #pragma unroll
        for (int ks = 0; ks < 2; ks++) {
            const uint32_t kb = (uint32_t)(ks * 32);
            uint32_t ahi[4][4], alo[4][4], bhi[4][2], blo[4][2];
            #pragma unroll
            for (int mt = 0; mt < 4; mt++) {
                uint32_t off = (uint32_t)((a_row + mt * 16) * (PROW * 2)) + kb + a_colb;
                ldsm4(ahi[mt], uAhi + off);
                ldsm4(alo[mt], uAlo + off);
            }
            {
                uint32_t t[4];
                uint32_t off0 = (uint32_t)(b_row * (PROW * 2)) + kb + b_colb;
                uint32_t off1 = (uint32_t)((b_row + 16) * (PROW * 2)) + kb + b_colb;
                ldsm4(t, uBhi + off0);
                bhi[0][0] = t[0]; bhi[0][1] = t[1]; bhi[1][0] = t[2]; bhi[1][1] = t[3];
                ldsm4(t, uBhi + off1);
                bhi[2][0] = t[0]; bhi[2][1] = t[1]; bhi[3][0] = t[2]; bhi[3][1] = t[3];
                ldsm4(t, uBlo + off0);
                blo[0][0] = t[0]; blo[0][1] = t[1]; blo[1][0] = t[2]; blo[1][1] = t[3];
                ldsm4(t, uBlo + off1);
                blo[2][0] = t[0]; blo[2][1] = t[1]; blo[3][0] = t[2]; blo[3][1] = t[3];
            }
            #pragma unroll
            for (int mt = 0; mt < 4; mt++)
                #pragma unroll
                for (int nt = 0; nt < 4; nt++) {
                    mma16816(acc[mt][nt], ahi[mt], bhi[nt]);
                    mma16816(acc[mt][nt], ahi[mt], blo[nt]);
                    mma16816(acc[mt][nt], alo[mt], bhi[nt]);
                }
        }
        __syncthreads();
    }

    // ---- epilogue: bias add + store (verbatim R8) ----
    const int g  = lane >> 2;
    const int tg = lane & 3;
    #pragma unroll
    for (int nt = 0; nt < 4; nt++) {
        const int ncol = n0 + warp_n * 32 + nt * 8 + tg * 2;
        const float2 bv2 = *reinterpret_cast<const float2*>(bias + ncol);
        #pragma unroll
        for (int mt = 0; mt < 4; mt++) {
            const int m = m0 + warp_m * 64 + mt * 16 + g;
            float2 o0 = make_float2(acc[mt][nt][0] + bv2.x, acc[mt][nt][1] + bv2.y);
            float2 o1 = make_float2(acc[mt][nt][2] + bv2.x, acc[mt][nt][3] + bv2.y);
            *reinterpret_cast<float2*>(out + (size_t)m * H_DIM + ncol)       = o0;
            *reinterpret_cast<float2*>(out + (size_t)(m + 8) * H_DIM + ncol) = o1;
        }
    }
}

// ---------------------------------------------------------------------------
// Mask compaction (R12, proven): per batch rank/index via ballot prefix sums.
// ---------------------------------------------------------------------------
__global__ void compact_kernel(const int* __restrict__ mask)
{
    const int b = blockIdx.x;
    const int tid = threadIdx.x;
    const int lane = tid & 31, wid = tid >> 5;

    int um = (mask[b * S_LEN + tid] == 0) ? 1 : 0;
    unsigned bal = __ballot_sync(0xffffffffu, um);
    int pre = __popc(bal & ((1u << lane) - 1));
    int wcnt = __popc(bal);

    __shared__ int wbase[32];
    __shared__ int wpre[32];
    if (lane == 0) wbase[wid] = wcnt;
    __syncthreads();
    if (wid == 0) {
        int v = wbase[lane];
        int x = v;
        #pragma unroll
        for (int o = 1; o < 32; o <<= 1) {
            int y = __shfl_up_sync(0xffffffffu, x, o);
            if (lane >= o) x += y;
        }
        wpre[lane] = x - v;
        if (lane == 31) g_nb[b] = x;
    }
    __syncthreads();

    int r = wpre[wid] + pre;
    g_rank[b][tid] = r;
    if (um) g_idx[b][r] = tid;
}

// ---------------------------------------------------------------------------
// Gather compacted K/V rows (R12, proven). grid (S_LEN, B_SZ), block 256.
// ---------------------------------------------------------------------------
__global__ void gather_kernel()
{
    const int b = blockIdx.y;
    const int j = blockIdx.x;
    if (j >= g_nb[b]) return;
    const int src = g_idx[b][j];
    const size_t so = ((size_t)b * S_LEN + src) * H_DIM;
    const size_t dof = ((size_t)b * S_LEN + j) * H_DIM;
    const float4* ks = reinterpret_cast<const float4*>(g_KL + so);
    const float4* vs = reinterpret_cast<const float4*>(g_VL + so);
    float4* kd = reinterpret_cast<float4*>(g_KC + dof);
    float4* vd = reinterpret_cast<float4*>(g_VC + dof);
    kd[threadIdx.x] = ks[threadIdx.x];
    vd[threadIdx.x] = vs[threadIdx.x];
}

// ---------------------------------------------------------------------------
// Fused attention over COMPACTED keys (R12, byte-exact proven version).
// ---------------------------------------------------------------------------
__global__ __launch_bounds__(256, 2) void attn_kernel(
    const int* __restrict__ mask, float* w, float* out_ctx)
{
    const int bh = blockIdx.y;
    const int b = bh >> 4;
    const int h = bh & 15;
    const int q0 = blockIdx.x * 128;
    const float* Qb = g_QL + (size_t)b * S_LEN * H_DIM + h * HDIM;
    const float* Kb = g_KC + (size_t)b * S_LEN * H_DIM + h * HDIM;  // compacted
    const float* Vb = g_VC + (size_t)b * S_LEN * H_DIM + h * HDIM;  // compacted
    float* W = w + (size_t)bh * S_LEN * S_LEN;

    __shared__ float As[16][132];
    __shared__ float Bs[16][132];
    __shared__ float sm_m[128];
    __shared__ float sm_il[128];
    __shared__ float smbuf[128][33];
    __shared__ int   sm_rank[S_LEN];
    __shared__ int   sm_um[S_LEN];

    const int tid = threadIdx.x;
    const int tx = tid & 15;
    const int ty = tid >> 4;

    const int nb = g_nb[b];
    const int ktiles = (nb + 127) >> 7;
    const int kc_end = ktiles * 128;

    float row_m[8], row_l[8];
    #pragma unroll
    for (int i = 0; i < 8; i++) { row_m[i] = -CUDART_INF_F; row_l[i] = 0.0f; }

    // ---------------- Phase 1: compacted scores + online stats ------------
    for (int kt = 0; kt < ktiles; kt++) {
        const int n0 = kt * 128;

        unsigned long long acc[8][4];
        #pragma unroll
        for (int i = 0; i < 8; i++)
            #pragma unroll
            for (int j = 0; j < 4; j++) acc[i][j] = 0ull;

        for (int k0 = 0; k0 < HDIM; k0 += 16) {
            #pragma unroll
            for (int l = 0; l < 2; l++) {
                int f = l * 256 + tid;
                int r = f >> 2, c4 = f & 3;
                const float4 v = *reinterpret_cast<const float4*>(
                    Qb + (size_t)(q0 + r) * H_DIM + k0 + c4 * 4);
                As[c4 * 4 + 0][r] = v.x; As[c4 * 4 + 1][r] = v.y;
                As[c4 * 4 + 2][r] = v.z; As[c4 * 4 + 3][r] = v.w;
            }
            #pragma unroll
            for (int l = 0; l < 2; l++) {
                int f = l * 256 + tid;
                int r = f >> 2, c4 = f & 3;
                const float4 v = *reinterpret_cast<const float4*>(
                    Kb + (size_t)(n0 + r) * H_DIM + k0 + c4 * 4);
                Bs[c4 * 4 + 0][r] = v.x; Bs[c4 * 4 + 1][r] = v.y;
                Bs[c4 * 4 + 2][r] = v.z; Bs[c4 * 4 + 3][r] = v.w;
            }
            __syncthreads();

            #pragma unroll
            for (int kk = 0; kk < 16; kk++) {
                float4 a0 = *reinterpret_cast<const float4*>(&As[kk][ty * 8]);
                float4 a1 = *reinterpret_cast<const float4*>(&As[kk][ty * 8 + 4]);
                unsigned long long aa[8];
                aa[0] = pack2(a0.x); aa[1] = pack2(a0.y); aa[2] = pack2(a0.z); aa[3] = pack2(a0.w);
                aa[4] = pack2(a1.x); aa[5] = pack2(a1.y); aa[6] = pack2(a1.z); aa[7] = pack2(a1.w);
                const unsigned long long* bp =
                    reinterpret_cast<const unsigned long long*>(&Bs[kk][tx * 8]);
                unsigned long long b0 = bp[0], b1 = bp[1], b2 = bp[2], b3 = bp[3];
                #pragma unroll
                for (int i = 0; i < 8; i++) {
                    acc[i][0] = ffma2(aa[i], b0, acc[i][0]);
                    acc[i][1] = ffma2(aa[i], b1, acc[i][1]);
                    acc[i][2] = ffma2(aa[i], b2, acc[i][2]);
                    acc[i][3] = ffma2(aa[i], b3, acc[i][3]);
                }
            }
            __syncthreads();
        }

        float madd[8];
        #pragma unroll
        for (int j = 0; j < 8; j++) {
            int cj = n0 + tx * 8 + j;
            madd[j] = (cj < nb) ? 0.0f : -1000000.0f;
        }

        float sacc[8][8];
        #pragma unroll
        for (int i = 0; i < 8; i++) {
            #pragma unroll
            for (int jj = 0; jj < 4; jj++) {
                float lo, hi;
                unpack2(acc[i][jj], lo, hi);
                sacc[i][2 * jj]     = lo * 0.125f + madd[2 * jj];
                sacc[i][2 * jj + 1] = hi * 0.125f + madd[2 * jj + 1];
            }
        }

        #pragma unroll
        for (int i = 0; i < 8; i++) {
            float tm = sacc[i][0];
            #pragma unroll
            for (int j = 1; j < 8; j++) tm = fmaxf(tm, sacc[i][j]);
            #pragma unroll
            for (int o = 8; o > 0; o >>= 1)
                tm = fmaxf(tm, __shfl_xor_sync(0xffffffffu, tm, o));
            float ts = 0.0f;
            #pragma unroll
            for (int j = 0; j < 8; j++) ts += __expf(sacc[i][j] - tm);
            #pragma unroll
            for (int o = 8; o > 0; o >>= 1)
                ts += __shfl_xor_sync(0xffffffffu, ts, o);

            float mn = fmaxf(row_m[i], tm);
            row_l[i] = row_l[i] * __expf(row_m[i] - mn) + ts * __expf(tm - mn);
            row_m[i] = mn;

            float4 s0 = make_float4(sacc[i][0], sacc[i][1], sacc[i][2], sacc[i][3]);
            float4 s1 = make_float4(sacc[i][4], sacc[i][5], sacc[i][6], sacc[i][7]);
            float* wp = W + (size_t)(q0 + ty * 8 + i) * S_LEN + n0 + tx * 8;
            *reinterpret_cast<float4*>(wp)     = s0;
            *reinterpret_cast<float4*>(wp + 4) = s1;
        }
    }

    if (tx == 0) {
        #pragma unroll
        for (int i = 0; i < 8; i++) {
            sm_m[ty * 8 + i]  = row_m[i];
            sm_il[ty * 8 + i] = 1.0f / row_l[i];
        }
    }
    __syncthreads();

    // ---------------- Phase 2: normalize compacted + P*Vc -----------------
    unsigned long long cacc[8][2];
    #pragma unroll
    for (int i = 0; i < 8; i++) { cacc[i][0] = 0ull; cacc[i][1] = 0ull; }

    for (int k0 = 0; k0 < kc_end; k0 += 16) {
        #pragma unroll
        for (int l = 0; l < 2; l++) {
            int f = l * 256 + tid;
            int r = f >> 2, c4 = f & 3;
            float* wp = W + (size_t)(q0 + r) * S_LEN + k0 + c4 * 4;
            float4 v = *reinterpret_cast<const float4*>(wp);
            const float mm = sm_m[r];
            const float il = sm_il[r];
            v.x = __expf(v.x - mm) * il;
            v.y = __expf(v.y - mm) * il;
            v.z = __expf(v.z - mm) * il;
            v.w = __expf(v.w - mm) * il;
            *reinterpret_cast<float4*>(wp) = v;
            As[c4 * 4 + 0][r] = v.x; As[c4 * 4 + 1][r] = v.y;
            As[c4 * 4 + 2][r] = v.z; As[c4 * 4 + 3][r] = v.w;
        }
        {
            int r = tid >> 4, c4 = tid & 15;
            const float4 v = *reinterpret_cast<const float4*>(
                Vb + (size_t)(k0 + r) * H_DIM + c4 * 4);
            *reinterpret_cast<float4*>(&Bs[r][c4 * 4]) = v;
        }
        __syncthreads();

        #pragma unroll
        for (int kk = 0; kk < 16; kk++) {
            float4 a0 = *reinterpret_cast<const float4*>(&As[kk][ty * 8]);
            float4 a1 = *reinterpret_cast<const float4*>(&As[kk][ty * 8 + 4]);
            unsigned long long aa[8];
            aa[0] = pack2(a0.x); aa[1] = pack2(a0.y); aa[2] = pack2(a0.z); aa[3] = pack2(a0.w);
            aa[4] = pack2(a1.x); aa[5] = pack2(a1.y); aa[6] = pack2(a1.z); aa[7] = pack2(a1.w);
            const unsigned long long* bp =
                reinterpret_cast<const unsigned long long*>(&Bs[kk][tx * 4]);
            unsigned long long b0 = bp[0], b1 = bp[1];
            #pragma unroll
            for (int i = 0; i < 8; i++) {
                cacc[i][0] = ffma2(aa[i], b0, cacc[i][0]);
                cacc[i][1] = ffma2(aa[i], b1, cacc[i][1]);
            }
        }
        __syncthreads();
    }

    #pragma unroll
    for (int i = 0; i < 8; i++) {
        int s = q0 + ty * 8 + i;
        float lo, hi;
        float4 o;
        unpack2(cacc[i][0], lo, hi); o.x = lo; o.y = hi;
        unpack2(cacc[i][1], lo, hi); o.z = lo; o.w = hi;
        *reinterpret_cast<float4*>(
            out_ctx + ((size_t)s * B_SZ + b) * H_DIM + h * HDIM + tx * 4) = o;
    }

    // ---------------- Phase 3: expand compacted -> dense weights ----------
    for (int n = tid; n < S_LEN; n += 256) {
        sm_rank[n] = g_rank[b][n];
        sm_um[n]   = (mask[b * S_LEN + n] == 0) ? 1 : 0;
    }
    __syncthreads();

    const int row  = tid >> 1;
    const int half = tid & 1;
    float* wrow = W + (size_t)(q0 + row) * S_LEN;

    for (int s = 31; s >= 0; s--) {
        const int n0 = s * 32;
        const int r0 = sm_rank[n0];
        const int r1 = (n0 + 32 < S_LEN) ? sm_rank[n0 + 32] : nb;
        const int width = r1 - r0;

        for (int i = half; i < width; i += 2)
            smbuf[row][i] = wrow[r0 + i];
        __syncthreads();

        #pragma unroll
        for (int i = 0; i < 4; i++) {
            const int nb4 = n0 + half * 16 + i * 4;
            float4 o;
            o.x = sm_um[nb4 + 0] ? smbuf[row][sm_rank[nb4 + 0] - r0] : 0.0f;
            o.y = sm_um[nb4 + 1] ? smbuf[row][sm_rank[nb4 + 1] - r0] : 0.0f;
            o.z = sm_um[nb4 + 2] ? smbuf[row][sm_rank[nb4 + 2] - r0] : 0.0f;
            o.w = sm_um[nb4 + 3] ? smbuf[row][sm_rank[nb4 + 3] - r0] : 0.0f;
            *reinterpret_cast<float4*>(wrow + nb4) = o;
        }
        __syncthreads();
    }
}

// ---------------------------------------------------------------------------
// Launch
// ---------------------------------------------------------------------------
extern "C" void kernel_launch(void* const* d_in, const int* in_sizes, int n_in,
                              void* d_out, int out_size)
{
    const float* q_states = (const float*)d_in[0];
    const float* k_states = (const float*)d_in[1];
    const float* v_states = (const float*)d_in[2];
    const int*   mask     = (const int*)  d_in[3];
    const float* Wq = (const float*)d_in[4];
    const float* bq = (const float*)d_in[5];
    const float* Wk = (const float*)d_in[6];
    const float* bk = (const float*)d_in[7];
    const float* Wv = (const float*)d_in[8];
    const float* bv = (const float*)d_in[9];

    float* out_ctx = (float*)d_out;                           // [S, B, H]
    float* out_w   = out_ctx + (size_t)S_LEN * B_SZ * H_DIM;  // [B, NH, S, S]

    // one-time fp32 -> bf16 hi/lo conversion of X and W
    preconv_kernel<<<3 * (M_ROWS + H_DIM), 256>>>(
        q_states, k_states, v_states, Wq, Wk, Wv);

    dim3 pg(H_DIM / 128, M_ROWS / 128, 3);   // (8, 64, 3)
    proj_mma_kernel<<<pg, 256>>>(bq, bk, bv);

    compact_kernel<<<B_SZ, 1024>>>(mask);
    gather_kernel<<<dim3(S_LEN, B_SZ), 256>>>();

    dim3 ag(S_LEN / 128, B_SZ * NHEAD);      // (8, 128)
    attn_kernel<<<ag, 256>>>(mask, out_w, out_ctx);
}

// round 15
// speedup vs baseline: 2.7580x; 1.0971x over previous
#include <cuda_runtime.h>
#include <cuda_bf16.h>
#include <math_constants.h>
#include <cstdint>

// Problem constants
#define S_LEN 1024
#define B_SZ  8
#define H_DIM 1024
#define NHEAD 16
#define HDIM  64
#define M_ROWS (B_SZ * S_LEN)   // 8192

// Scratch for projected Q/K/V, [B*S, H] with m = b*S_LEN + s.
__device__ float g_QL[(size_t)M_ROWS * H_DIM];
__device__ float g_KL[(size_t)M_ROWS * H_DIM];
__device__ float g_VL[(size_t)M_ROWS * H_DIM];
// Compacted V rows (fp32) and compacted K rows (bf16 hi/lo), per batch.
__device__ float g_VC[(size_t)M_ROWS * H_DIM];
__device__ __nv_bfloat16 g_KCH[(size_t)M_ROWS * H_DIM];
__device__ __nv_bfloat16 g_KCL[(size_t)M_ROWS * H_DIM];
// Q in bf16 hi/lo (for HMMA scores).
__device__ __nv_bfloat16 g_QH2[(size_t)M_ROWS * H_DIM];
__device__ __nv_bfloat16 g_QL2[(size_t)M_ROWS * H_DIM];
__device__ int g_nb[B_SZ];
__device__ int g_idx[B_SZ][S_LEN];    // compacted j -> dense index
__device__ int g_rank[B_SZ][S_LEN];   // dense n -> # unmasked before n

// Pre-converted bf16 hi/lo operands for the HMMA projection GEMMs.
__device__ __nv_bfloat16 g_XH[3][(size_t)M_ROWS * H_DIM];
__device__ __nv_bfloat16 g_XL[3][(size_t)M_ROWS * H_DIM];
__device__ __nv_bfloat16 g_WH[3][(size_t)H_DIM * H_DIM];
__device__ __nv_bfloat16 g_WL[3][(size_t)H_DIM * H_DIM];

// ---------------------------------------------------------------------------
// Helpers
// ---------------------------------------------------------------------------
__device__ __forceinline__ uint32_t smem_to_u32(const void* p) {
    uint32_t a;
    asm("{ .reg .u64 t; cvta.to.shared.u64 t, %1; cvt.u32.u64 %0, t; }"
        : "=r"(a) : "l"(p));
    return a;
}

__device__ __forceinline__ void mma16816(float* c, const uint32_t* a, const uint32_t* b)
{
    asm volatile(
        "mma.sync.aligned.m16n8k16.row.col.f32.bf16.bf16.f32 "
        "{%0,%1,%2,%3},{%4,%5,%6,%7},{%8,%9},{%0,%1,%2,%3};"
        : "+f"(c[0]), "+f"(c[1]), "+f"(c[2]), "+f"(c[3])
        : "r"(a[0]), "r"(a[1]), "r"(a[2]), "r"(a[3]), "r"(b[0]), "r"(b[1]));
}

__device__ __forceinline__ void ldsm4(uint32_t* r, uint32_t addr)
{
    asm volatile("ldmatrix.sync.aligned.m8n8.x4.shared.b16 {%0,%1,%2,%3},[%4];"
                 : "=r"(r[0]), "=r"(r[1]), "=r"(r[2]), "=r"(r[3]) : "r"(addr));
}

__device__ __forceinline__ unsigned long long ffma2(
    unsigned long long a, unsigned long long b, unsigned long long c)
{
    unsigned long long d;
    asm("fma.rn.f32x2 %0, %1, %2, %3;" : "=l"(d) : "l"(a), "l"(b), "l"(c));
    return d;
}
__device__ __forceinline__ unsigned long long pack2(float x)
{
    unsigned long long d;
    asm("mov.b64 %0, {%1, %1};" : "=l"(d) : "f"(x));
    return d;
}
__device__ __forceinline__ void unpack2(unsigned long long v, float& lo, float& hi)
{
    asm("mov.b64 {%0, %1}, %2;" : "=f"(lo), "=f"(hi) : "l"(v));
}

__device__ __forceinline__ void cvt4_split(
    float4 v, uint32_t& h0, uint32_t& h1, uint32_t& l0, uint32_t& l1)
{
    __nv_bfloat16 hx = __float2bfloat16_rn(v.x);
    __nv_bfloat16 hy = __float2bfloat16_rn(v.y);
    __nv_bfloat16 hz = __float2bfloat16_rn(v.z);
    __nv_bfloat16 hw = __float2bfloat16_rn(v.w);
    h0 = (uint32_t)__bfloat16_as_ushort(hx) | ((uint32_t)__bfloat16_as_ushort(hy) << 16);
    h1 = (uint32_t)__bfloat16_as_ushort(hz) | ((uint32_t)__bfloat16_as_ushort(hw) << 16);
    __nv_bfloat16 lx = __float2bfloat16_rn(v.x - __bfloat162float(hx));
    __nv_bfloat16 ly = __float2bfloat16_rn(v.y - __bfloat162float(hy));
    __nv_bfloat16 lz = __float2bfloat16_rn(v.z - __bfloat162float(hz));
    __nv_bfloat16 lw = __float2bfloat16_rn(v.w - __bfloat162float(hw));
    l0 = (uint32_t)__bfloat16_as_ushort(lx) | ((uint32_t)__bfloat16_as_ushort(ly) << 16);
    l1 = (uint32_t)__bfloat16_as_ushort(lz) | ((uint32_t)__bfloat16_as_ushort(lw) << 16);
}

// ---------------------------------------------------------------------------
// Pre-convert X (seq-first fp32) and W to bf16 hi/lo (R13, proven).
// ---------------------------------------------------------------------------
__global__ __launch_bounds__(256) void preconv_kernel(
    const float* __restrict__ Xq, const float* __restrict__ Xk,
    const float* __restrict__ Xv,
    const float* __restrict__ Wq, const float* __restrict__ Wk,
    const float* __restrict__ Wv)
{
    const int row = blockIdx.x;          // 0..27647
    const int z = row / 9216;
    const int r = row % 9216;
    const int col = threadIdx.x * 4;

    const float* src;
    __nv_bfloat16 *dh, *dl;
    if (r < M_ROWS) {
        const float* X = (z == 0) ? Xq : ((z == 1) ? Xk : Xv);
        const int b = r >> 10, s = r & 1023;
        src = X + ((size_t)(s * B_SZ + b)) * H_DIM;
        dh = g_XH[z] + (size_t)r * H_DIM;
        dl = g_XL[z] + (size_t)r * H_DIM;
    } else {
        const int rw = r - M_ROWS;
        const float* W = (z == 0) ? Wq : ((z == 1) ? Wk : Wv);
        src = W + (size_t)rw * H_DIM;
        dh = g_WH[z] + (size_t)rw * H_DIM;
        dl = g_WL[z] + (size_t)rw * H_DIM;
    }

    float4 v = *reinterpret_cast<const float4*>(src + col);
    uint32_t h0, h1, l0, l1;
    cvt4_split(v, h0, h1, l0, l1);
    *reinterpret_cast<uint2*>(dh + col) = make_uint2(h0, h1);
    *reinterpret_cast<uint2*>(dl + col) = make_uint2(l0, l1);
}

// ---------------------------------------------------------------------------
// Convert projected Q (fp32) -> bf16 hi/lo. grid M_ROWS, block 256.
// ---------------------------------------------------------------------------
__global__ __launch_bounds__(256) void qconv_kernel()
{
    const int row = blockIdx.x;
    const int col = threadIdx.x * 4;
    float4 v = *reinterpret_cast<const float4*>(g_QL + (size_t)row * H_DIM + col);
    uint32_t h0, h1, l0, l1;
    cvt4_split(v, h0, h1, l0, l1);
    *reinterpret_cast<uint2*>(g_QH2 + (size_t)row * H_DIM + col) = make_uint2(h0, h1);
    *reinterpret_cast<uint2*>(g_QL2 + (size_t)row * H_DIM + col) = make_uint2(l0, l1);
}

// ---------------------------------------------------------------------------
// Projection GEMM via mma.sync (R13, byte-exact proven version).
// ---------------------------------------------------------------------------
#define PROW 40   // padded row stride in bf16 elems (80B)

__global__ __launch_bounds__(256) void proj_mma_kernel(
    const float* __restrict__ bq, const float* __restrict__ bk,
    const float* __restrict__ bv)
{
    __shared__ __align__(16) uint16_t sAhi[128 * PROW];
    __shared__ __align__(16) uint16_t sAlo[128 * PROW];
    __shared__ __align__(16) uint16_t sBhi[128 * PROW];
    __shared__ __align__(16) uint16_t sBlo[128 * PROW];

    const int z = blockIdx.z;
    const float* bias = (z == 0) ? bq : ((z == 1) ? bk : bv);
    float* out        = (z == 0) ? g_QL : ((z == 1) ? g_KL : g_VL);

    const int m0 = blockIdx.y * 128;
    const int n0 = blockIdx.x * 128;

    const __nv_bfloat16* Ah = g_XH[z] + (size_t)m0 * H_DIM;
    const __nv_bfloat16* Al = g_XL[z] + (size_t)m0 * H_DIM;
    const __nv_bfloat16* Bh = g_WH[z] + (size_t)n0 * H_DIM;
    const __nv_bfloat16* Bl = g_WL[z] + (size_t)n0 * H_DIM;

    const int tid  = threadIdx.x;
    const int lane = tid & 31;
    const int wid  = tid >> 5;
    const int warp_m = wid & 1;
    const int warp_n = wid >> 1;

    const uint32_t uAhi = smem_to_u32(sAhi);
    const uint32_t uAlo = smem_to_u32(sAlo);
    const uint32_t uBhi = smem_to_u32(sBhi);
    const uint32_t uBlo = smem_to_u32(sBlo);

    float acc[4][4][4];
    #pragma unroll
    for (int i = 0; i < 4; i++)
        #pragma unroll
        for (int j = 0; j < 4; j++)
            #pragma unroll
            for (int k = 0; k < 4; k++) acc[i][j][k] = 0.0f;

    const int sr = tid >> 1;
    const int hf = tid & 1;

    const int a_row = warp_m * 64 + (lane & 15);
    const uint32_t a_colb = (uint32_t)((lane >> 4) << 4);
    const int b_row = warp_n * 32 + (lane & 7) + ((lane & 16) ? 8 : 0);
    const uint32_t b_colb = (uint32_t)((lane & 8) ? 16 : 0);

    for (int c = 0; c < H_DIM / 32; c++) {
        {
            const size_t go = (size_t)sr * H_DIM + c * 32 + hf * 16;
            const int    so = sr * PROW + hf * 16;
            #pragma unroll
            for (int i = 0; i < 4; i++) {
                *reinterpret_cast<uint2*>(&sAhi[so + i * 4]) =
                    *reinterpret_cast<const uint2*>(Ah + go + i * 4);
                *reinterpret_cast<uint2*>(&sAlo[so + i * 4]) =
                    *reinterpret_cast<const uint2*>(Al + go + i * 4);
                *reinterpret_cast<uint2*>(&sBhi[so + i * 4]) =
                    *reinterpret_cast<const uint2*>(Bh + go + i * 4);
                *reinterpret_cast<uint2*>(&sBlo[so + i * 4]) =
                    *reinterpret_cast<const uint2*>(Bl + go + i * 4);
            }
        }
        __syncthreads();

        #pragma unroll
        for (int ks = 0; ks < 2; ks++) {
            const uint32_t kb = (uint32_t)(ks * 32);
            uint32_t ahi[4][4], alo[4][4], bhi[4][2], blo[4][2];
            #pragma unroll
            for (int mt = 0; mt < 4; mt++) {
                uint32_t off = (uint32_t)((a_row + mt * 16) * (PROW * 2)) + kb + a_colb;
                ldsm4(ahi[mt], uAhi + off);
                ldsm4(alo[mt], uAlo + off);
            }
            {
                uint32_t t[4];
                uint32_t off0 = (uint32_t)(b_row * (PROW * 2)) + kb + b_colb;
                uint32_t off1 = (uint32_t)((b_row + 16) * (PROW * 2)) + kb + b_colb;
                ldsm4(t, uBhi + off0);
                bhi[0][0] = t[0]; bhi[0][1] = t[1]; bhi[1][0] = t[2]; bhi[1][1] = t[3];
                ldsm4(t, uBhi + off1);
                bhi[2][0] = t[0]; bhi[2][1] = t[1]; bhi[3][0] = t[2]; bhi[3][1] = t[3];
                ldsm4(t, uBlo + off0);
                blo[0][0] = t[0]; blo[0][1] = t[1]; blo[1][0] = t[2]; blo[1][1] = t[3];
                ldsm4(t, uBlo + off1);
                blo[2][0] = t[0]; blo[2][1] = t[1]; blo[3][0] = t[2]; blo[3][1] = t[3];
            }
            #pragma unroll
            for (int mt = 0; mt < 4; mt++)
                #pragma unroll
                for (int nt = 0; nt < 4; nt++) {
                    mma16816(acc[mt][nt], ahi[mt], bhi[nt]);
                    mma16816(acc[mt][nt], ahi[mt], blo[nt]);
                    mma16816(acc[mt][nt], alo[mt], bhi[nt]);
                }
        }
        __syncthreads();
    }

    const int g  = lane >> 2;
    const int tg = lane & 3;
    #pragma unroll
    for (int nt = 0; nt < 4; nt++) {
        const int ncol = n0 + warp_n * 32 + nt * 8 + tg * 2;
        const float2 bv2 = *reinterpret_cast<const float2*>(bias + ncol);
        #pragma unroll
        for (int mt = 0; mt < 4; mt++) {
            const int m = m0 + warp_m * 64 + mt * 16 + g;
            float2 o0 = make_float2(acc[mt][nt][0] + bv2.x, acc[mt][nt][1] + bv2.y);
            float2 o1 = make_float2(acc[mt][nt][2] + bv2.x, acc[mt][nt][3] + bv2.y);
            *reinterpret_cast<float2*>(out + (size_t)m * H_DIM + ncol)       = o0;
            *reinterpret_cast<float2*>(out + (size_t)(m + 8) * H_DIM + ncol) = o1;
        }
    }
}

// ---------------------------------------------------------------------------
// Mask compaction (R12, proven).
// ---------------------------------------------------------------------------
__global__ void compact_kernel(const int* __restrict__ mask)
{
    const int b = blockIdx.x;
    const int tid = threadIdx.x;
    const int lane = tid & 31, wid = tid >> 5;

    int um = (mask[b * S_LEN + tid] == 0) ? 1 : 0;
    unsigned bal = __ballot_sync(0xffffffffu, um);
    int pre = __popc(bal & ((1u << lane) - 1));
    int wcnt = __popc(bal);

    __shared__ int wbase[32];
    __shared__ int wpre[32];
    if (lane == 0) wbase[wid] = wcnt;
    __syncthreads();
    if (wid == 0) {
        int v = wbase[lane];
        int x = v;
        #pragma unroll
        for (int o = 1; o < 32; o <<= 1) {
            int y = __shfl_up_sync(0xffffffffu, x, o);
            if (lane >= o) x += y;
        }
        wpre[lane] = x - v;
        if (lane == 31) g_nb[b] = x;
    }
    __syncthreads();

    int r = wpre[wid] + pre;
    g_rank[b][tid] = r;
    if (um) g_idx[b][r] = tid;
}

// ---------------------------------------------------------------------------
// Gather compacted rows: K as bf16 hi/lo, V as fp32. grid (S_LEN, B_SZ).
// ---------------------------------------------------------------------------
__global__ void gather_kernel()
{
    const int b = blockIdx.y;
    const int j = blockIdx.x;
    if (j >= g_nb[b]) return;
    const int src = g_idx[b][j];
    const size_t so = ((size_t)b * S_LEN + src) * H_DIM;
    const size_t dof = ((size_t)b * S_LEN + j) * H_DIM;
    const int c = threadIdx.x * 4;

    float4 kv = *reinterpret_cast<const float4*>(g_KL + so + c);
    uint32_t h0, h1, l0, l1;
    cvt4_split(kv, h0, h1, l0, l1);
    *reinterpret_cast<uint2*>(g_KCH + dof + c) = make_uint2(h0, h1);
    *reinterpret_cast<uint2*>(g_KCL + dof + c) = make_uint2(l0, l1);

    *reinterpret_cast<float4*>(g_VC + dof + c) =
        *reinterpret_cast<const float4*>(g_VL + so + c);
}

// ---------------------------------------------------------------------------
// Fused attention over COMPACTED keys.
//   Phase 1: scores via HMMA split-bf16 (3 terms), 8 warps partition the
//     128 q-rows; quad-level softmax stats. (Staging bug from R14 fixed:
//     4 x uint4 at 8-element stride = full 32-element coverage.)
//   Phase 2/3: byte-identical to R12 (normalize+PV, expand to dense).
// ---------------------------------------------------------------------------
#define SM_QH 0
#define SM_QL 18432
#define SM_KH 36864
#define SM_KL 55296
#define SM_P2A 0
#define SM_P2B 8448
#define SM_BUF 0
#define SM_RANK 16896
#define SM_UM 20992
#define SM_MOFF 73728
#define SM_ILOFF 74240
#define ATTN_SMEM 74752
#define QKROW 72   // row stride in bf16 elems (144B)

__global__ __launch_bounds__(256, 2) void attn_kernel(
    const int* __restrict__ mask, float* w, float* out_ctx)
{
    extern __shared__ char smx[];
    float* sm_m  = reinterpret_cast<float*>(smx + SM_MOFF);
    float* sm_il = reinterpret_cast<float*>(smx + SM_ILOFF);

    const int bh = blockIdx.y;
    const int b = bh >> 4;
    const int h = bh & 15;
    const int q0 = blockIdx.x * 128;
    const float* Vb = g_VC + (size_t)b * S_LEN * H_DIM + h * HDIM;
    float* W = w + (size_t)bh * S_LEN * S_LEN;

    const int tid = threadIdx.x;
    const int lane = tid & 31;
    const int wp  = tid >> 5;
    const int g   = lane >> 2;
    const int tg  = lane & 3;

    const int nb = g_nb[b];
    const int ktiles = (nb + 127) >> 7;
    const int kc_end = ktiles * 128;

    // ================= Phase 1: HMMA scores + online stats =================
    {
        uint16_t* sQh = reinterpret_cast<uint16_t*>(smx + SM_QH);
        uint16_t* sQl = reinterpret_cast<uint16_t*>(smx + SM_QL);
        uint16_t* sKh = reinterpret_cast<uint16_t*>(smx + SM_KH);
        uint16_t* sKl = reinterpret_cast<uint16_t*>(smx + SM_KL);
        const uint32_t uQh = smem_to_u32(sQh);
        const uint32_t uQl = smem_to_u32(sQl);
        const uint32_t uKh = smem_to_u32(sKh);
        const uint32_t uKl = smem_to_u32(sKl);

        // stage Q tile once: 128 rows x 64 bf16 (hi/lo), row stride 72.
        // 4 x uint4 (8 bf16 each) at stride 8 = full 32-col coverage (R14 fix).
        {
            const int row = tid >> 1, hf = tid & 1;
            const size_t go = ((size_t)(b * S_LEN + q0 + row)) * H_DIM + h * HDIM + hf * 32;
            const int so = row * QKROW + hf * 32;
            #pragma unroll
            for (int i = 0; i < 4; i++) {
                *reinterpret_cast<uint4*>(&sQh[so + i * 8]) =
                    *reinterpret_cast<const uint4*>(g_QH2 + go + i * 8);
                *reinterpret_cast<uint4*>(&sQl[so + i * 8]) =
                    *reinterpret_cast<const uint4*>(g_QL2 + go + i * 8);
            }
        }

        float row_m0 = -CUDART_INF_F, row_l0 = 0.0f;
        float row_m1 = -CUDART_INF_F, row_l1 = 0.0f;

        const uint32_t a_base = (uint32_t)((wp * 16 + (lane & 15)) * (QKROW * 2))
                              + (uint32_t)((lane >> 4) << 4);
        const uint32_t b_rowsel = (uint32_t)(((lane & 7) + ((lane & 16) ? 8 : 0)) * (QKROW * 2))
                                + (uint32_t)((lane & 8) ? 16 : 0);

        for (int kt = 0; kt < ktiles; kt++) {
            // stage K tile: rows kt*128 + (0..127), 64 bf16 hi/lo (fixed stride)
            {
                const int row = tid >> 1, hf = tid & 1;
                const size_t go = ((size_t)(b * S_LEN + kt * 128 + row)) * H_DIM
                                + h * HDIM + hf * 32;
                const int so = row * QKROW + hf * 32;
                #pragma unroll
                for (int i = 0; i < 4; i++) {
                    *reinterpret_cast<uint4*>(&sKh[so + i * 8]) =
                        *reinterpret_cast<const uint4*>(g_KCH + go + i * 8);
                    *reinterpret_cast<uint4*>(&sKl[so + i * 8]) =
                        *reinterpret_cast<const uint4*>(g_KCL + go + i * 8);
                }
            }
            __syncthreads();

            float acc[16][4];
            #pragma unroll
            for (int nt = 0; nt < 16; nt++)
                #pragma unroll
                for (int q = 0; q < 4; q++) acc[nt][q] = 0.0f;

            #pragma unroll
            for (int ks = 0; ks < 4; ks++) {
                const uint32_t kb = (uint32_t)(ks * 32);
                uint32_t ah[4], al[4];
                ldsm4(ah, uQh + a_base + kb);
                ldsm4(al, uQl + a_base + kb);
                #pragma unroll
                for (int p = 0; p < 8; p++) {
                    uint32_t koff = (uint32_t)(p * 16 * (QKROW * 2)) + b_rowsel + kb;
                    uint32_t bh4[4], bl4[4];
                    ldsm4(bh4, uKh + koff);
                    ldsm4(bl4, uKl + koff);
                    mma16816(acc[2 * p],     ah, bh4);
                    mma16816(acc[2 * p],     ah, bl4);
                    mma16816(acc[2 * p],     al, bh4);
                    mma16816(acc[2 * p + 1], ah, bh4 + 2);
                    mma16816(acc[2 * p + 1], ah, bl4 + 2);
                    mma16816(acc[2 * p + 1], al, bh4 + 2);
                }
            }
            __syncthreads();   // K tile free for next kt

            // scale + out-of-range mask
            #pragma unroll
            for (int nt = 0; nt < 16; nt++) {
                const int c0 = kt * 128 + nt * 8 + tg * 2;
                const float m0 = (c0     < nb) ? 0.0f : -1000000.0f;
                const float m1 = (c0 + 1 < nb) ? 0.0f : -1000000.0f;
                acc[nt][0] = acc[nt][0] * 0.125f + m0;
                acc[nt][1] = acc[nt][1] * 0.125f + m1;
                acc[nt][2] = acc[nt][2] * 0.125f + m0;
                acc[nt][3] = acc[nt][3] * 0.125f + m1;
            }

            // row stats (row g: c0/c1; row g+8: c2/c3), quad reduction
            float tm0 = -CUDART_INF_F, tm1 = -CUDART_INF_F;
            #pragma unroll
            for (int nt = 0; nt < 16; nt++) {
                tm0 = fmaxf(tm0, fmaxf(acc[nt][0], acc[nt][1]));
                tm1 = fmaxf(tm1, fmaxf(acc[nt][2], acc[nt][3]));
            }
            tm0 = fmaxf(tm0, __shfl_xor_sync(0xffffffffu, tm0, 1));
            tm0 = fmaxf(tm0, __shfl_xor_sync(0xffffffffu, tm0, 2));
            tm1 = fmaxf(tm1, __shfl_xor_sync(0xffffffffu, tm1, 1));
            tm1 = fmaxf(tm1, __shfl_xor_sync(0xffffffffu, tm1, 2));

            float ts0 = 0.0f, ts1 = 0.0f;
            #pragma unroll
            for (int nt = 0; nt < 16; nt++) {
                ts0 += __expf(acc[nt][0] - tm0) + __expf(acc[nt][1] - tm0);
                ts1 += __expf(acc[nt][2] - tm1) + __expf(acc[nt][3] - tm1);
            }
            ts0 += __shfl_xor_sync(0xffffffffu, ts0, 1);
            ts0 += __shfl_xor_sync(0xffffffffu, ts0, 2);
            ts1 += __shfl_xor_sync(0xffffffffu, ts1, 1);
            ts1 += __shfl_xor_sync(0xffffffffu, ts1, 2);

            float mn0 = fmaxf(row_m0, tm0);
            row_l0 = row_l0 * __expf(row_m0 - mn0) + ts0 * __expf(tm0 - mn0);
            row_m0 = mn0;
            float mn1 = fmaxf(row_m1, tm1);
            row_l1 = row_l1 * __expf(row_m1 - mn1) + ts1 * __expf(tm1 - mn1);
            row_m1 = mn1;

            // store raw scaled+masked scores
            float* wr0 = W + (size_t)(q0 + wp * 16 + g) * S_LEN + kt * 128 + tg * 2;
            float* wr1 = wr0 + (size_t)8 * S_LEN;
            #pragma unroll
            for (int nt = 0; nt < 16; nt++) {
                *reinterpret_cast<float2*>(wr0 + nt * 8) = make_float2(acc[nt][0], acc[nt][1]);
                *reinterpret_cast<float2*>(wr1 + nt * 8) = make_float2(acc[nt][2], acc[nt][3]);
            }
        }

        if (tg == 0) {
            sm_m[wp * 16 + g]      = row_m0;
            sm_il[wp * 16 + g]     = 1.0f / row_l0;
            sm_m[wp * 16 + g + 8]  = row_m1;
            sm_il[wp * 16 + g + 8] = 1.0f / row_l1;
        }
    }
    __syncthreads();

    // ================= Phase 2: normalize compacted + P*Vc (R12) ==========
    {
        float (*As)[132] = reinterpret_cast<float(*)[132]>(smx + SM_P2A);
        float (*Bs)[132] = reinterpret_cast<float(*)[132]>(smx + SM_P2B);
        const int tx = tid & 15;
        const int ty = tid >> 4;

        unsigned long long cacc[8][2];
        #pragma unroll
        for (int i = 0; i < 8; i++) { cacc[i][0] = 0ull; cacc[i][1] = 0ull; }

        for (int k0 = 0; k0 < kc_end; k0 += 16) {
            #pragma unroll
            for (int l = 0; l < 2; l++) {
                int f = l * 256 + tid;
                int r = f >> 2, c4 = f & 3;
                float* wpp = W + (size_t)(q0 + r) * S_LEN + k0 + c4 * 4;
                float4 v = *reinterpret_cast<const float4*>(wpp);
                const float mm = sm_m[r];
                const float il = sm_il[r];
                v.x = __expf(v.x - mm) * il;
                v.y = __expf(v.y - mm) * il;
                v.z = __expf(v.z - mm) * il;
                v.w = __expf(v.w - mm) * il;
                *reinterpret_cast<float4*>(wpp) = v;
                As[c4 * 4 + 0][r] = v.x; As[c4 * 4 + 1][r] = v.y;
                As[c4 * 4 + 2][r] = v.z; As[c4 * 4 + 3][r] = v.w;
            }
            {
                int r = tid >> 4, c4 = tid & 15;
                const float4 v = *reinterpret_cast<const float4*>(
                    Vb + (size_t)(k0 + r) * H_DIM + c4 * 4);
                *reinterpret_cast<float4*>(&Bs[r][c4 * 4]) = v;
            }
            __syncthreads();

            #pragma unroll
            for (int kk = 0; kk < 16; kk++) {
                float4 a0 = *reinterpret_cast<const float4*>(&As[kk][ty * 8]);
                float4 a1 = *reinterpret_cast<const float4*>(&As[kk][ty * 8 + 4]);
                unsigned long long aa[8];
                aa[0] = pack2(a0.x); aa[1] = pack2(a0.y); aa[2] = pack2(a0.z); aa[3] = pack2(a0.w);
                aa[4] = pack2(a1.x); aa[5] = pack2(a1.y); aa[6] = pack2(a1.z); aa[7] = pack2(a1.w);
                const unsigned long long* bp =
                    reinterpret_cast<const unsigned long long*>(&Bs[kk][tx * 4]);
                unsigned long long b0 = bp[0], b1 = bp[1];
                #pragma unroll
                for (int i = 0; i < 8; i++) {
                    cacc[i][0] = ffma2(aa[i], b0, cacc[i][0]);
                    cacc[i][1] = ffma2(aa[i], b1, cacc[i][1]);
                }
            }
            __syncthreads();
        }

        #pragma unroll
        for (int i = 0; i < 8; i++) {
            int s = q0 + ty * 8 + i;
            float lo, hi;
            float4 o;
            unpack2(cacc[i][0], lo, hi); o.x = lo; o.y = hi;
            unpack2(cacc[i][1], lo, hi); o.z = lo; o.w = hi;
            *reinterpret_cast<float4*>(
                out_ctx + ((size_t)s * B_SZ + b) * H_DIM + h * HDIM + tx * 4) = o;
        }
    }
    __syncthreads();

    // ================= Phase 3: expand compacted -> dense (R12) ===========
    {
        float (*smbuf)[33] = reinterpret_cast<float(*)[33]>(smx + SM_BUF);
        int* sm_rank = reinterpret_cast<int*>(smx + SM_RANK);
        int* sm_um   = reinterpret_cast<int*>(smx + SM_UM);

        for (int n = tid; n < S_LEN; n += 256) {
            sm_rank[n] = g_rank[b][n];
            sm_um[n]   = (mask[b * S_LEN + n] == 0) ? 1 : 0;
        }
        __syncthreads();

        const int row  = tid >> 1;
        const int half = tid & 1;
        float* wrow = W + (size_t)(q0 + row) * S_LEN;

        for (int s = 31; s >= 0; s--) {
            const int n0 = s * 32;
            const int r0 = sm_rank[n0];
            const int r1 = (n0 + 32 < S_LEN) ? sm_rank[n0 + 32] : nb;
            const int width = r1 - r0;

            for (int i = half; i < width; i += 2)
                smbuf[row][i] = wrow[r0 + i];
            __syncthreads();

            #pragma unroll
            for (int i = 0; i < 4; i++) {
                const int nb4 = n0 + half * 16 + i * 4;
                float4 o;
                o.x = sm_um[nb4 + 0] ? smbuf[row][sm_rank[nb4 + 0] - r0] : 0.0f;
                o.y = sm_um[nb4 + 1] ? smbuf[row][sm_rank[nb4 + 1] - r0] : 0.0f;
                o.z = sm_um[nb4 + 2] ? smbuf[row][sm_rank[nb4 + 2] - r0] : 0.0f;
                o.w = sm_um[nb4 + 3] ? smbuf[row][sm_rank[nb4 + 3] - r0] : 0.0f;
                *reinterpret_cast<float4*>(wrow + nb4) = o;
            }
            __syncthreads();
        }
    }
}

// ---------------------------------------------------------------------------
// Launch
// ---------------------------------------------------------------------------
extern "C" void kernel_launch(void* const* d_in, const int* in_sizes, int n_in,
                              void* d_out, int out_size)
{
    const float* q_states = (const float*)d_in[0];
    const float* k_states = (const float*)d_in[1];
    const float* v_states = (const float*)d_in[2];
    const int*   mask     = (const int*)  d_in[3];
    const float* Wq = (const float*)d_in[4];
    const float* bq = (const float*)d_in[5];
    const float* Wk = (const float*)d_in[6];
    const float* bk = (const float*)d_in[7];
    const float* Wv = (const float*)d_in[8];
    const float* bv = (const float*)d_in[9];

    float* out_ctx = (float*)d_out;                           // [S, B, H]
    float* out_w   = out_ctx + (size_t)S_LEN * B_SZ * H_DIM;  // [B, NH, S, S]

    static int smem_set = 0;
    if (!smem_set) {
        cudaFuncSetAttribute(attn_kernel,
                             cudaFuncAttributeMaxDynamicSharedMemorySize,
                             ATTN_SMEM);
        smem_set = 1;
    }

    // one-time fp32 -> bf16 hi/lo conversion of X and W
    preconv_kernel<<<3 * (M_ROWS + H_DIM), 256>>>(
        q_states, k_states, v_states, Wq, Wk, Wv);

    dim3 pg(H_DIM / 128, M_ROWS / 128, 3);   // (8, 64, 3)
    proj_mma_kernel<<<pg, 256>>>(bq, bk, bv);

    qconv_kernel<<<M_ROWS, 256>>>();
    compact_kernel<<<B_SZ, 1024>>>(mask);
    gather_kernel<<<dim3(S_LEN, B_SZ), 256>>>();

    dim3 ag(S_LEN / 128, B_SZ * NHEAD);      // (8, 128)
    attn_kernel<<<ag, 256, ATTN_SMEM>>>(mask, out_w, out_ctx);
}

// round 16
// speedup vs baseline: 2.7627x; 1.0017x over previous
#include <cuda_runtime.h>
#include <cuda_bf16.h>
#include <math_constants.h>
#include <cstdint>

// Problem constants
#define S_LEN 1024
#define B_SZ  8
#define H_DIM 1024
#define NHEAD 16
#define HDIM  64
#define M_ROWS (B_SZ * S_LEN)   // 8192

// Scratch for projected Q/K/V, [B*S, H] with m = b*S_LEN + s.
__device__ float g_QL[(size_t)M_ROWS * H_DIM];
__device__ float g_KL[(size_t)M_ROWS * H_DIM];
__device__ float g_VL[(size_t)M_ROWS * H_DIM];
// Compacted K rows (bf16 hi/lo), per batch.
__device__ __nv_bfloat16 g_KCH[(size_t)M_ROWS * H_DIM];
__device__ __nv_bfloat16 g_KCL[(size_t)M_ROWS * H_DIM];
// Compacted V, TRANSPOSED per batch: [b][d (H_DIM)][j (S_LEN)], bf16 hi/lo.
// Unwritten (j >= nb) entries stay zero (device globals zero-init; nb is
// identical on every replay so stale-garbage never appears).
__device__ __nv_bfloat16 g_VTH[(size_t)B_SZ * H_DIM * S_LEN];
__device__ __nv_bfloat16 g_VTL[(size_t)B_SZ * H_DIM * S_LEN];
// Q in bf16 hi/lo (for HMMA scores) — written by proj epilogue (z==0).
__device__ __nv_bfloat16 g_QH2[(size_t)M_ROWS * H_DIM];
__device__ __nv_bfloat16 g_QL2[(size_t)M_ROWS * H_DIM];
__device__ int g_nb[B_SZ];
__device__ int g_idx[B_SZ][S_LEN];    // compacted j -> dense index
__device__ int g_rank[B_SZ][S_LEN];   // dense n -> # unmasked before n

// Pre-converted bf16 hi/lo operands for the HMMA projection GEMMs.
__device__ __nv_bfloat16 g_XH[3][(size_t)M_ROWS * H_DIM];
__device__ __nv_bfloat16 g_XL[3][(size_t)M_ROWS * H_DIM];
__device__ __nv_bfloat16 g_WH[3][(size_t)H_DIM * H_DIM];
__device__ __nv_bfloat16 g_WL[3][(size_t)H_DIM * H_DIM];

// ---------------------------------------------------------------------------
// Helpers
// ---------------------------------------------------------------------------
__device__ __forceinline__ uint32_t smem_to_u32(const void* p) {
    uint32_t a;
    asm("{ .reg .u64 t; cvta.to.shared.u64 t, %1; cvt.u32.u64 %0, t; }"
        : "=r"(a) : "l"(p));
    return a;
}

__device__ __forceinline__ void mma16816(float* c, const uint32_t* a, const uint32_t* b)
{
    asm volatile(
        "mma.sync.aligned.m16n8k16.row.col.f32.bf16.bf16.f32 "
        "{%0,%1,%2,%3},{%4,%5,%6,%7},{%8,%9},{%0,%1,%2,%3};"
        : "+f"(c[0]), "+f"(c[1]), "+f"(c[2]), "+f"(c[3])
        : "r"(a[0]), "r"(a[1]), "r"(a[2]), "r"(a[3]), "r"(b[0]), "r"(b[1]));
}

__device__ __forceinline__ void ldsm4(uint32_t* r, uint32_t addr)
{
    asm volatile("ldmatrix.sync.aligned.m8n8.x4.shared.b16 {%0,%1,%2,%3},[%4];"
                 : "=r"(r[0]), "=r"(r[1]), "=r"(r[2]), "=r"(r[3]) : "r"(addr));
}

__device__ __forceinline__ void cvt4_split(
    float4 v, uint32_t& h0, uint32_t& h1, uint32_t& l0, uint32_t& l1)
{
    __nv_bfloat16 hx = __float2bfloat16_rn(v.x);
    __nv_bfloat16 hy = __float2bfloat16_rn(v.y);
    __nv_bfloat16 hz = __float2bfloat16_rn(v.z);
    __nv_bfloat16 hw = __float2bfloat16_rn(v.w);
    h0 = (uint32_t)__bfloat16_as_ushort(hx) | ((uint32_t)__bfloat16_as_ushort(hy) << 16);
    h1 = (uint32_t)__bfloat16_as_ushort(hz) | ((uint32_t)__bfloat16_as_ushort(hw) << 16);
    __nv_bfloat16 lx = __float2bfloat16_rn(v.x - __bfloat162float(hx));
    __nv_bfloat16 ly = __float2bfloat16_rn(v.y - __bfloat162float(hy));
    __nv_bfloat16 lz = __float2bfloat16_rn(v.z - __bfloat162float(hz));
    __nv_bfloat16 lw = __float2bfloat16_rn(v.w - __bfloat162float(hw));
    l0 = (uint32_t)__bfloat16_as_ushort(lx) | ((uint32_t)__bfloat16_as_ushort(ly) << 16);
    l1 = (uint32_t)__bfloat16_as_ushort(lz) | ((uint32_t)__bfloat16_as_ushort(lw) << 16);
}

__device__ __forceinline__ void cvt2_split(float2 v, uint32_t& h, uint32_t& l)
{
    __nv_bfloat16 hx = __float2bfloat16_rn(v.x);
    __nv_bfloat16 hy = __float2bfloat16_rn(v.y);
    h = (uint32_t)__bfloat16_as_ushort(hx) | ((uint32_t)__bfloat16_as_ushort(hy) << 16);
    __nv_bfloat16 lx = __float2bfloat16_rn(v.x - __bfloat162float(hx));
    __nv_bfloat16 ly = __float2bfloat16_rn(v.y - __bfloat162float(hy));
    l = (uint32_t)__bfloat16_as_ushort(lx) | ((uint32_t)__bfloat16_as_ushort(ly) << 16);
}

// ---------------------------------------------------------------------------
// Pre-convert X (seq-first fp32) and W to bf16 hi/lo (R13, proven).
// ---------------------------------------------------------------------------
__global__ __launch_bounds__(256) void preconv_kernel(
    const float* __restrict__ Xq, const float* __restrict__ Xk,
    const float* __restrict__ Xv,
    const float* __restrict__ Wq, const float* __restrict__ Wk,
    const float* __restrict__ Wv)
{
    const int row = blockIdx.x;          // 0..27647
    const int z = row / 9216;
    const int r = row % 9216;
    const int col = threadIdx.x * 4;

    const float* src;
    __nv_bfloat16 *dh, *dl;
    if (r < M_ROWS) {
        const float* X = (z == 0) ? Xq : ((z == 1) ? Xk : Xv);
        const int b = r >> 10, s = r & 1023;
        src = X + ((size_t)(s * B_SZ + b)) * H_DIM;
        dh = g_XH[z] + (size_t)r * H_DIM;
        dl = g_XL[z] + (size_t)r * H_DIM;
    } else {
        const int rw = r - M_ROWS;
        const float* W = (z == 0) ? Wq : ((z == 1) ? Wk : Wv);
        src = W + (size_t)rw * H_DIM;
        dh = g_WH[z] + (size_t)rw * H_DIM;
        dl = g_WL[z] + (size_t)rw * H_DIM;
    }

    float4 v = *reinterpret_cast<const float4*>(src + col);
    uint32_t h0, h1, l0, l1;
    cvt4_split(v, h0, h1, l0, l1);
    *reinterpret_cast<uint2*>(dh + col) = make_uint2(h0, h1);
    *reinterpret_cast<uint2*>(dl + col) = make_uint2(l0, l1);
}

// ---------------------------------------------------------------------------
// Projection GEMM via mma.sync (R13, proven) + z==0 writes Q bf16 hi/lo
// directly from the epilogue (replaces the qconv pass).
// ---------------------------------------------------------------------------
#define PROW 40   // padded row stride in bf16 elems (80B)

__global__ __launch_bounds__(256) void proj_mma_kernel(
    const float* __restrict__ bq, const float* __restrict__ bk,
    const float* __restrict__ bv)
{
    __shared__ __align__(16) uint16_t sAhi[128 * PROW];
    __shared__ __align__(16) uint16_t sAlo[128 * PROW];
    __shared__ __align__(16) uint16_t sBhi[128 * PROW];
    __shared__ __align__(16) uint16_t sBlo[128 * PROW];

    const int z = blockIdx.z;
    const float* bias = (z == 0) ? bq : ((z == 1) ? bk : bv);
    float* out        = (z == 0) ? g_QL : ((z == 1) ? g_KL : g_VL);

    const int m0 = blockIdx.y * 128;
    const int n0 = blockIdx.x * 128;

    const __nv_bfloat16* Ah = g_XH[z] + (size_t)m0 * H_DIM;
    const __nv_bfloat16* Al = g_XL[z] + (size_t)m0 * H_DIM;
    const __nv_bfloat16* Bh = g_WH[z] + (size_t)n0 * H_DIM;
    const __nv_bfloat16* Bl = g_WL[z] + (size_t)n0 * H_DIM;

    const int tid  = threadIdx.x;
    const int lane = tid & 31;
    const int wid  = tid >> 5;
    const int warp_m = wid & 1;
    const int warp_n = wid >> 1;

    const uint32_t uAhi = smem_to_u32(sAhi);
    const uint32_t uAlo = smem_to_u32(sAlo);
    const uint32_t uBhi = smem_to_u32(sBhi);
    const uint32_t uBlo = smem_to_u32(sBlo);

    float acc[4][4][4];
    #pragma unroll
    for (int i = 0; i < 4; i++)
        #pragma unroll
        for (int j = 0; j < 4; j++)
            #pragma unroll
            for (int k = 0; k < 4; k++) acc[i][j][k] = 0.0f;

    const int sr = tid >> 1;
    const int hf = tid & 1;

    const int a_row = warp_m * 64 + (lane & 15);
    const uint32_t a_colb = (uint32_t)((lane >> 4) << 4);
    const int b_row = warp_n * 32 + (lane & 7) + ((lane & 16) ? 8 : 0);
    const uint32_t b_colb = (uint32_t)((lane & 8) ? 16 : 0);

    for (int c = 0; c < H_DIM / 32; c++) {
        {
            const size_t go = (size_t)sr * H_DIM + c * 32 + hf * 16;
            const int    so = sr * PROW + hf * 16;
            #pragma unroll
            for (int i = 0; i < 4; i++) {
                *reinterpret_cast<uint2*>(&sAhi[so + i * 4]) =
                    *reinterpret_cast<const uint2*>(Ah + go + i * 4);
                *reinterpret_cast<uint2*>(&sAlo[so + i * 4]) =
                    *reinterpret_cast<const uint2*>(Al + go + i * 4);
                *reinterpret_cast<uint2*>(&sBhi[so + i * 4]) =
                    *reinterpret_cast<const uint2*>(Bh + go + i * 4);
                *reinterpret_cast<uint2*>(&sBlo[so + i * 4]) =
                    *reinterpret_cast<const uint2*>(Bl + go + i * 4);
            }
        }
        __syncthreads();

        #pragma unroll
        for (int ks = 0; ks < 2; ks++) {
            const uint32_t kb = (uint32_t)(ks * 32);
            uint32_t ahi[4][4], alo[4][4], bhi[4][2], blo[4][2];
            #pragma unroll
            for (int mt = 0; mt < 4; mt++) {
                uint32_t off = (uint32_t)((a_row + mt * 16) * (PROW * 2)) + kb + a_colb;
                ldsm4(ahi[mt], uAhi + off);
                ldsm4(alo[mt], uAlo + off);
            }
            {
                uint32_t t[4];
                uint32_t off0 = (uint32_t)(b_row * (PROW * 2)) + kb + b_colb;
                uint32_t off1 = (uint32_t)((b_row + 16) * (PROW * 2)) + kb + b_colb;
                ldsm4(t, uBhi + off0);
                bhi[0][0] = t[0]; bhi[0][1] = t[1]; bhi[1][0] = t[2]; bhi[1][1] = t[3];
                ldsm4(t, uBhi + off1);
                bhi[2][0] = t[0]; bhi[2][1] = t[1]; bhi[3][0] = t[2]; bhi[3][1] = t[3];
                ldsm4(t, uBlo + off0);
                blo[0][0] = t[0]; blo[0][1] = t[1]; blo[1][0] = t[2]; blo[1][1] = t[3];
                ldsm4(t, uBlo + off1);
                blo[2][0] = t[0]; blo[2][1] = t[1]; blo[3][0] = t[2]; blo[3][1] = t[3];
            }
            #pragma unroll
            for (int mt = 0; mt < 4; mt++)
                #pragma unroll
                for (int nt = 0; nt < 4; nt++) {
                    mma16816(acc[mt][nt], ahi[mt], bhi[nt]);
                    mma16816(acc[mt][nt], ahi[mt], blo[nt]);
                    mma16816(acc[mt][nt], alo[mt], bhi[nt]);
                }
        }
        __syncthreads();
    }

    const int g  = lane >> 2;
    const int tg = lane & 3;
    #pragma unroll
    for (int nt = 0; nt < 4; nt++) {
        const int ncol = n0 + warp_n * 32 + nt * 8 + tg * 2;
        const float2 bv2 = *reinterpret_cast<const float2*>(bias + ncol);
        #pragma unroll
        for (int mt = 0; mt < 4; mt++) {
            const int m = m0 + warp_m * 64 + mt * 16 + g;
            float2 o0 = make_float2(acc[mt][nt][0] + bv2.x, acc[mt][nt][1] + bv2.y);
            float2 o1 = make_float2(acc[mt][nt][2] + bv2.x, acc[mt][nt][3] + bv2.y);
            *reinterpret_cast<float2*>(out + (size_t)m * H_DIM + ncol)       = o0;
            *reinterpret_cast<float2*>(out + (size_t)(m + 8) * H_DIM + ncol) = o1;
            if (z == 0) {   // fold Q fp32->bf16 hi/lo conversion into epilogue
                uint32_t h, l;
                cvt2_split(o0, h, l);
                *reinterpret_cast<uint32_t*>(&g_QH2[(size_t)m * H_DIM + ncol]) = h;
                *reinterpret_cast<uint32_t*>(&g_QL2[(size_t)m * H_DIM + ncol]) = l;
                cvt2_split(o1, h, l);
                *reinterpret_cast<uint32_t*>(&g_QH2[(size_t)(m + 8) * H_DIM + ncol]) = h;
                *reinterpret_cast<uint32_t*>(&g_QL2[(size_t)(m + 8) * H_DIM + ncol]) = l;
            }
        }
    }
}

// ---------------------------------------------------------------------------
// Mask compaction (R12, proven).
// ---------------------------------------------------------------------------
__global__ void compact_kernel(const int* __restrict__ mask)
{
    const int b = blockIdx.x;
    const int tid = threadIdx.x;
    const int lane = tid & 31, wid = tid >> 5;

    int um = (mask[b * S_LEN + tid] == 0) ? 1 : 0;
    unsigned bal = __ballot_sync(0xffffffffu, um);
    int pre = __popc(bal & ((1u << lane) - 1));
    int wcnt = __popc(bal);

    __shared__ int wbase[32];
    __shared__ int wpre[32];
    if (lane == 0) wbase[wid] = wcnt;
    __syncthreads();
    if (wid == 0) {
        int v = wbase[lane];
        int x = v;
        #pragma unroll
        for (int o = 1; o < 32; o <<= 1) {
            int y = __shfl_up_sync(0xffffffffu, x, o);
            if (lane >= o) x += y;
        }
        wpre[lane] = x - v;
        if (lane == 31) g_nb[b] = x;
    }
    __syncthreads();

    int r = wpre[wid] + pre;
    g_rank[b][tid] = r;
    if (um) g_idx[b][r] = tid;
}

// ---------------------------------------------------------------------------
// Gather compacted K rows as bf16 hi/lo. grid (S_LEN, B_SZ), block 256.
// ---------------------------------------------------------------------------
__global__ void gather_kernel()
{
    const int b = blockIdx.y;
    const int j = blockIdx.x;
    if (j >= g_nb[b]) return;
    const int src = g_idx[b][j];
    const size_t so = ((size_t)b * S_LEN + src) * H_DIM;
    const size_t dof = ((size_t)b * S_LEN + j) * H_DIM;
    const int c = threadIdx.x * 4;

    float4 kv = *reinterpret_cast<const float4*>(g_KL + so + c);
    uint32_t h0, h1, l0, l1;
    cvt4_split(kv, h0, h1, l0, l1);
    *reinterpret_cast<uint2*>(g_KCH + dof + c) = make_uint2(h0, h1);
    *reinterpret_cast<uint2*>(g_KCL + dof + c) = make_uint2(l0, l1);
}

// ---------------------------------------------------------------------------
// Gather + TRANSPOSE compacted V to [b][d][j] bf16 hi/lo via 32x32 smem tile.
// grid (32 jt, 32 dt, B_SZ), block 256. Tiles fully beyond nb: skipped
// (buffer stays zero). Partial tiles: j>=nb lanes contribute zeros.
// ---------------------------------------------------------------------------
__global__ __launch_bounds__(256) void vtrans_kernel()
{
    const int jt = blockIdx.x;
    const int dt = blockIdx.y;
    const int b  = blockIdx.z;
    const int nb = g_nb[b];
    if (jt * 32 >= nb) return;

    __shared__ uint16_t sh[32][36];
    __shared__ uint16_t sl[32][36];

    const int tid = threadIdx.x;
    const int jl = tid >> 3;            // 0..31 local j
    const int c4 = (tid & 7) * 4;       // 0..28 local d

    const int j = jt * 32 + jl;
    float4 v = make_float4(0.f, 0.f, 0.f, 0.f);
    if (j < nb) {
        const int src = g_idx[b][j];
        v = *reinterpret_cast<const float4*>(
            g_VL + ((size_t)(b * S_LEN + src)) * H_DIM + dt * 32 + c4);
    }
    uint32_t h0, h1, l0, l1;
    cvt4_split(v, h0, h1, l0, l1);
    *reinterpret_cast<uint2*>(&sh[jl][c4]) = make_uint2(h0, h1);
    *reinterpret_cast<uint2*>(&sl[jl][c4]) = make_uint2(l0, l1);
    __syncthreads();

    const int dl = tid >> 3;            // 0..31 local d
    const int jc4 = (tid & 7) * 4;      // 0..28 local j
    uint32_t w0 = (uint32_t)sh[jc4 + 0][dl] | ((uint32_t)sh[jc4 + 1][dl] << 16);
    uint32_t w1 = (uint32_t)sh[jc4 + 2][dl] | ((uint32_t)sh[jc4 + 3][dl] << 16);
    const size_t dof = ((size_t)(b * H_DIM + dt * 32 + dl)) * S_LEN + jt * 32 + jc4;
    *reinterpret_cast<uint2*>(g_VTH + dof) = make_uint2(w0, w1);
    w0 = (uint32_t)sl[jc4 + 0][dl] | ((uint32_t)sl[jc4 + 1][dl] << 16);
    w1 = (uint32_t)sl[jc4 + 2][dl] | ((uint32_t)sl[jc4 + 3][dl] << 16);
    *reinterpret_cast<uint2*>(g_VTL + dof) = make_uint2(w0, w1);
}

// ---------------------------------------------------------------------------
// Fused attention over COMPACTED keys.
//   Phase 1 (R15, proven): HMMA split-bf16 scores, quad-level stats.
//   Phase 2 (NEW): normalize raw W in place (same as before), convert P to
//     bf16 hi/lo in smem, PV via 3-term HMMA against transposed V (fragment
//     addressing identical to phase 1's verified K path, 4 row-groups).
//   Phase 3 (R12, proven): expand compacted -> dense weights in place.
// ---------------------------------------------------------------------------
#define SM_QH 0
#define SM_QL 18432
#define SM_KH 36864
#define SM_KL 55296
#define SM_PH 0          // phase 2: P hi (128 x 72 bf16)
#define SM_PL 18432      // phase 2: P lo
#define SM_VH 36864      // phase 2: V^T hi (64 x 72 bf16)
#define SM_VL 46080      // phase 2: V^T lo
#define SM_BUF 0
#define SM_RANK 16896
#define SM_UM 20992
#define SM_MOFF 73728
#define SM_ILOFF 74240
#define ATTN_SMEM 74752
#define QKROW 72   // row stride in bf16 elems (144B)

__global__ __launch_bounds__(256, 2) void attn_kernel(
    const int* __restrict__ mask, float* w, float* out_ctx)
{
    extern __shared__ char smx[];
    float* sm_m  = reinterpret_cast<float*>(smx + SM_MOFF);
    float* sm_il = reinterpret_cast<float*>(smx + SM_ILOFF);

    const int bh = blockIdx.y;
    const int b = bh >> 4;
    const int h = bh & 15;
    const int q0 = blockIdx.x * 128;
    float* W = w + (size_t)bh * S_LEN * S_LEN;

    const int tid = threadIdx.x;
    const int lane = tid & 31;
    const int wp  = tid >> 5;
    const int g   = lane >> 2;
    const int tg  = lane & 3;

    const int nb = g_nb[b];
    const int ktiles = (nb + 127) >> 7;
    const int kc_end = ktiles * 128;

    // ================= Phase 1: HMMA scores + online stats (R15) ==========
    {
        uint16_t* sQh = reinterpret_cast<uint16_t*>(smx + SM_QH);
        uint16_t* sQl = reinterpret_cast<uint16_t*>(smx + SM_QL);
        uint16_t* sKh = reinterpret_cast<uint16_t*>(smx + SM_KH);
        uint16_t* sKl = reinterpret_cast<uint16_t*>(smx + SM_KL);
        const uint32_t uQh = smem_to_u32(sQh);
        const uint32_t uQl = smem_to_u32(sQl);
        const uint32_t uKh = smem_to_u32(sKh);
        const uint32_t uKl = smem_to_u32(sKl);

        {
            const int row = tid >> 1, hf = tid & 1;
            const size_t go = ((size_t)(b * S_LEN + q0 + row)) * H_DIM + h * HDIM + hf * 32;
            const int so = row * QKROW + hf * 32;
            #pragma unroll
            for (int i = 0; i < 4; i++) {
                *reinterpret_cast<uint4*>(&sQh[so + i * 8]) =
                    *reinterpret_cast<const uint4*>(g_QH2 + go + i * 8);
                *reinterpret_cast<uint4*>(&sQl[so + i * 8]) =
                    *reinterpret_cast<const uint4*>(g_QL2 + go + i * 8);
            }
        }

        float row_m0 = -CUDART_INF_F, row_l0 = 0.0f;
        float row_m1 = -CUDART_INF_F, row_l1 = 0.0f;

        const uint32_t a_base = (uint32_t)((wp * 16 + (lane & 15)) * (QKROW * 2))
                              + (uint32_t)((lane >> 4) << 4);
        const uint32_t b_rowsel = (uint32_t)(((lane & 7) + ((lane & 16) ? 8 : 0)) * (QKROW * 2))
                                + (uint32_t)((lane & 8) ? 16 : 0);

        for (int kt = 0; kt < ktiles; kt++) {
            {
                const int row = tid >> 1, hf = tid & 1;
                const size_t go = ((size_t)(b * S_LEN + kt * 128 + row)) * H_DIM
                                + h * HDIM + hf * 32;
                const int so = row * QKROW + hf * 32;
                #pragma unroll
                for (int i = 0; i < 4; i++) {
                    *reinterpret_cast<uint4*>(&sKh[so + i * 8]) =
                        *reinterpret_cast<const uint4*>(g_KCH + go + i * 8);
                    *reinterpret_cast<uint4*>(&sKl[so + i * 8]) =
                        *reinterpret_cast<const uint4*>(g_KCL + go + i * 8);
                }
            }
            __syncthreads();

            float acc[16][4];
            #pragma unroll
            for (int nt = 0; nt < 16; nt++)
                #pragma unroll
                for (int q = 0; q < 4; q++) acc[nt][q] = 0.0f;

            #pragma unroll
            for (int ks = 0; ks < 4; ks++) {
                const uint32_t kb = (uint32_t)(ks * 32);
                uint32_t ah[4], al[4];
                ldsm4(ah, uQh + a_base + kb);
                ldsm4(al, uQl + a_base + kb);
                #pragma unroll
                for (int p = 0; p < 8; p++) {
                    uint32_t koff = (uint32_t)(p * 16 * (QKROW * 2)) + b_rowsel + kb;
                    uint32_t bh4[4], bl4[4];
                    ldsm4(bh4, uKh + koff);
                    ldsm4(bl4, uKl + koff);
                    mma16816(acc[2 * p],     ah, bh4);
                    mma16816(acc[2 * p],     ah, bl4);
                    mma16816(acc[2 * p],     al, bh4);
                    mma16816(acc[2 * p + 1], ah, bh4 + 2);
                    mma16816(acc[2 * p + 1], ah, bl4 + 2);
                    mma16816(acc[2 * p + 1], al, bh4 + 2);
                }
            }
            __syncthreads();

            #pragma unroll
            for (int nt = 0; nt < 16; nt++) {
                const int c0 = kt * 128 + nt * 8 + tg * 2;
                const float m0 = (c0     < nb) ? 0.0f : -1000000.0f;
                const float m1 = (c0 + 1 < nb) ? 0.0f : -1000000.0f;
                acc[nt][0] = acc[nt][0] * 0.125f + m0;
                acc[nt][1] = acc[nt][1] * 0.125f + m1;
                acc[nt][2] = acc[nt][2] * 0.125f + m0;
                acc[nt][3] = acc[nt][3] * 0.125f + m1;
            }

            float tm0 = -CUDART_INF_F, tm1 = -CUDART_INF_F;
            #pragma unroll
            for (int nt = 0; nt < 16; nt++) {
                tm0 = fmaxf(tm0, fmaxf(acc[nt][0], acc[nt][1]));
                tm1 = fmaxf(tm1, fmaxf(acc[nt][2], acc[nt][3]));
            }
            tm0 = fmaxf(tm0, __shfl_xor_sync(0xffffffffu, tm0, 1));
            tm0 = fmaxf(tm0, __shfl_xor_sync(0xffffffffu, tm0, 2));
            tm1 = fmaxf(tm1, __shfl_xor_sync(0xffffffffu, tm1, 1));
            tm1 = fmaxf(tm1, __shfl_xor_sync(0xffffffffu, tm1, 2));

            float ts0 = 0.0f, ts1 = 0.0f;
            #pragma unroll
            for (int nt = 0; nt < 16; nt++) {
                ts0 += __expf(acc[nt][0] - tm0) + __expf(acc[nt][1] - tm0);
                ts1 += __expf(acc[nt][2] - tm1) + __expf(acc[nt][3] - tm1);
            }
            ts0 += __shfl_xor_sync(0xffffffffu, ts0, 1);
            ts0 += __shfl_xor_sync(0xffffffffu, ts0, 2);
            ts1 += __shfl_xor_sync(0xffffffffu, ts1, 1);
            ts1 += __shfl_xor_sync(0xffffffffu, ts1, 2);

            float mn0 = fmaxf(row_m0, tm0);
            row_l0 = row_l0 * __expf(row_m0 - mn0) + ts0 * __expf(tm0 - mn0);
            row_m0 = mn0;
            float mn1 = fmaxf(row_m1, tm1);
            row_l1 = row_l1 * __expf(row_m1 - mn1) + ts1 * __expf(tm1 - mn1);
            row_m1 = mn1;

            float* wr0 = W + (size_t)(q0 + wp * 16 + g) * S_LEN + kt * 128 + tg * 2;
            float* wr1 = wr0 + (size_t)8 * S_LEN;
            #pragma unroll
            for (int nt = 0; nt < 16; nt++) {
                *reinterpret_cast<float2*>(wr0 + nt * 8) = make_float2(acc[nt][0], acc[nt][1]);
                *reinterpret_cast<float2*>(wr1 + nt * 8) = make_float2(acc[nt][2], acc[nt][3]);
            }
        }

        if (tg == 0) {
            sm_m[wp * 16 + g]      = row_m0;
            sm_il[wp * 16 + g]     = 1.0f / row_l0;
            sm_m[wp * 16 + g + 8]  = row_m1;
            sm_il[wp * 16 + g + 8] = 1.0f / row_l1;
        }
    }
    __syncthreads();

    // ================= Phase 2: normalize + PV via 3-term HMMA ============
    {
        uint16_t* sPh = reinterpret_cast<uint16_t*>(smx + SM_PH);
        uint16_t* sPl = reinterpret_cast<uint16_t*>(smx + SM_PL);
        uint16_t* sVh = reinterpret_cast<uint16_t*>(smx + SM_VH);
        uint16_t* sVl = reinterpret_cast<uint16_t*>(smx + SM_VL);
        const uint32_t uPh = smem_to_u32(sPh);
        const uint32_t uPl = smem_to_u32(sPl);
        const uint32_t uVh = smem_to_u32(sVh);
        const uint32_t uVl = smem_to_u32(sVl);

        const __nv_bfloat16* VTh = g_VTH + ((size_t)(b * H_DIM + h * HDIM)) * S_LEN;
        const __nv_bfloat16* VTl = g_VTL + ((size_t)(b * H_DIM + h * HDIM)) * S_LEN;

        float cacc[8][4];
        #pragma unroll
        for (int nt = 0; nt < 8; nt++)
            #pragma unroll
            for (int q = 0; q < 4; q++) cacc[nt][q] = 0.0f;

        const uint32_t pa_base = (uint32_t)((wp * 16 + (lane & 15)) * (QKROW * 2))
                               + (uint32_t)((lane >> 4) << 4);
        const uint32_t vb_rowsel = (uint32_t)(((lane & 7) + ((lane & 16) ? 8 : 0)) * (QKROW * 2))
                                 + (uint32_t)((lane & 8) ? 16 : 0);

        for (int k0 = 0; k0 < kc_end; k0 += 64) {
            // stage P: normalize raw W in place + convert to bf16 hi/lo
            {
                const int r = tid >> 1, hf = tid & 1;
                const float mm = sm_m[r];
                const float il = sm_il[r];
                float* wrow = W + (size_t)(q0 + r) * S_LEN + k0 + hf * 32;
                uint16_t* ph = &sPh[r * QKROW + hf * 32];
                uint16_t* pl = &sPl[r * QKROW + hf * 32];
                #pragma unroll
                for (int i = 0; i < 8; i++) {
                    float4 v = *reinterpret_cast<const float4*>(wrow + i * 4);
                    v.x = __expf(v.x - mm) * il;
                    v.y = __expf(v.y - mm) * il;
                    v.z = __expf(v.z - mm) * il;
                    v.w = __expf(v.w - mm) * il;
                    *reinterpret_cast<float4*>(wrow + i * 4) = v;
                    uint32_t h0, h1, l0, l1;
                    cvt4_split(v, h0, h1, l0, l1);
                    *reinterpret_cast<uint2*>(ph + i * 4) = make_uint2(h0, h1);
                    *reinterpret_cast<uint2*>(pl + i * 4) = make_uint2(l0, l1);
                }
            }
            // stage V^T: 64 d-rows x 64 k-cols, pure bf16 copy
            {
                const int r = tid >> 2, q4 = tid & 3;
                const size_t go = (size_t)r * S_LEN + k0 + q4 * 16;
                const int so = r * QKROW + q4 * 16;
                *reinterpret_cast<uint4*>(&sVh[so])     = *reinterpret_cast<const uint4*>(VTh + go);
                *reinterpret_cast<uint4*>(&sVh[so + 8]) = *reinterpret_cast<const uint4*>(VTh + go + 8);
                *reinterpret_cast<uint4*>(&sVl[so])     = *reinterpret_cast<const uint4*>(VTl + go);
                *reinterpret_cast<uint4*>(&sVl[so + 8]) = *reinterpret_cast<const uint4*>(VTl + go + 8);
            }
            __syncthreads();

            #pragma unroll
            for (int ks = 0; ks < 4; ks++) {
                const uint32_t kb = (uint32_t)(ks * 32);
                uint32_t ph4[4], pl4[4];
                ldsm4(ph4, uPh + pa_base + kb);
                ldsm4(pl4, uPl + pa_base + kb);
                #pragma unroll
                for (int p = 0; p < 4; p++) {
                    uint32_t koff = (uint32_t)(p * 16 * (QKROW * 2)) + vb_rowsel + kb;
                    uint32_t vh4[4], vl4[4];
                    ldsm4(vh4, uVh + koff);
                    ldsm4(vl4, uVl + koff);
                    mma16816(cacc[2 * p],     ph4, vh4);
                    mma16816(cacc[2 * p],     ph4, vl4);
                    mma16816(cacc[2 * p],     pl4, vh4);
                    mma16816(cacc[2 * p + 1], ph4, vh4 + 2);
                    mma16816(cacc[2 * p + 1], ph4, vl4 + 2);
                    mma16816(cacc[2 * p + 1], pl4, vh4 + 2);
                }
            }
            __syncthreads();
        }

        // ctx epilogue: row g / g+8 of warp's 16-row strip, d = nt*8 + tg*2
        const int s0 = q0 + wp * 16 + g;
        #pragma unroll
        for (int nt = 0; nt < 8; nt++) {
            const int d = nt * 8 + tg * 2;
            *reinterpret_cast<float2*>(
                out_ctx + ((size_t)s0 * B_SZ + b) * H_DIM + h * HDIM + d) =
                make_float2(cacc[nt][0], cacc[nt][1]);
            *reinterpret_cast<float2*>(
                out_ctx + ((size_t)(s0 + 8) * B_SZ + b) * H_DIM + h * HDIM + d) =
                make_float2(cacc[nt][2], cacc[nt][3]);
        }
    }
    __syncthreads();

    // ================= Phase 3: expand compacted -> dense (R12) ===========
    {
        float (*smbuf)[33] = reinterpret_cast<float(*)[33]>(smx + SM_BUF);
        int* sm_rank = reinterpret_cast<int*>(smx + SM_RANK);
        int* sm_um   = reinterpret_cast<int*>(smx + SM_UM);

        for (int n = tid; n < S_LEN; n += 256) {
            sm_rank[n] = g_rank[b][n];
            sm_um[n]   = (mask[b * S_LEN + n] == 0) ? 1 : 0;
        }
        __syncthreads();

        const int row  = tid >> 1;
        const int half = tid & 1;
        float* wrow = W + (size_t)(q0 + row) * S_LEN;

        for (int s = 31; s >= 0; s--) {
            const int n0 = s * 32;
            const int r0 = sm_rank[n0];
            const int r1 = (n0 + 32 < S_LEN) ? sm_rank[n0 + 32] : nb;
            const int width = r1 - r0;

            for (int i = half; i < width; i += 2)
                smbuf[row][i] = wrow[r0 + i];
            __syncthreads();

            #pragma unroll
            for (int i = 0; i < 4; i++) {
                const int nb4 = n0 + half * 16 + i * 4;
                float4 o;
                o.x = sm_um[nb4 + 0] ? smbuf[row][sm_rank[nb4 + 0] - r0] : 0.0f;
                o.y = sm_um[nb4 + 1] ? smbuf[row][sm_rank[nb4 + 1] - r0] : 0.0f;
                o.z = sm_um[nb4 + 2] ? smbuf[row][sm_rank[nb4 + 2] - r0] : 0.0f;
                o.w = sm_um[nb4 + 3] ? smbuf[row][sm_rank[nb4 + 3] - r0] : 0.0f;
                *reinterpret_cast<float4*>(wrow + nb4) = o;
            }
            __syncthreads();
        }
    }
}

// ---------------------------------------------------------------------------
// Launch
// ---------------------------------------------------------------------------
extern "C" void kernel_launch(void* const* d_in, const int* in_sizes, int n_in,
                              void* d_out, int out_size)
{
    const float* q_states = (const float*)d_in[0];
    const float* k_states = (const float*)d_in[1];
    const float* v_states = (const float*)d_in[2];
    const int*   mask     = (const int*)  d_in[3];
    const float* Wq = (const float*)d_in[4];
    const float* bq = (const float*)d_in[5];
    const float* Wk = (const float*)d_in[6];
    const float* bk = (const float*)d_in[7];
    const float* Wv = (const float*)d_in[8];
    const float* bv = (const float*)d_in[9];

    float* out_ctx = (float*)d_out;                           // [S, B, H]
    float* out_w   = out_ctx + (size_t)S_LEN * B_SZ * H_DIM;  // [B, NH, S, S]

    static int smem_set = 0;
    if (!smem_set) {
        cudaFuncSetAttribute(attn_kernel,
                             cudaFuncAttributeMaxDynamicSharedMemorySize,
                             ATTN_SMEM);
        smem_set = 1;
    }

    preconv_kernel<<<3 * (M_ROWS + H_DIM), 256>>>(
        q_states, k_states, v_states, Wq, Wk, Wv);

    dim3 pg(H_DIM / 128, M_ROWS / 128, 3);   // (8, 64, 3)
    proj_mma_kernel<<<pg, 256>>>(bq, bk, bv);

    compact_kernel<<<B_SZ, 1024>>>(mask);
    gather_kernel<<<dim3(S_LEN, B_SZ), 256>>>();
    vtrans_kernel<<<dim3(32, 32, B_SZ), 256>>>();

    dim3 ag(S_LEN / 128, B_SZ * NHEAD);      // (8, 128)
    attn_kernel<<<ag, 256, ATTN_SMEM>>>(mask, out_w, out_ctx);
}

// round 17
// speedup vs baseline: 3.1928x; 1.1557x over previous
#include <cuda_runtime.h>
#include <cuda_bf16.h>
#include <math_constants.h>
#include <cstdint>

// Problem constants
#define S_LEN 1024
#define B_SZ  8
#define H_DIM 1024
#define NHEAD 16
#define HDIM  64
#define M_ROWS (B_SZ * S_LEN)   // 8192

// Scratch for projected Q/K/V, [B*S, H] with m = b*S_LEN + s.
__device__ float g_QL[(size_t)M_ROWS * H_DIM];
__device__ float g_KL[(size_t)M_ROWS * H_DIM];
__device__ float g_VL[(size_t)M_ROWS * H_DIM];
// Compacted K rows (bf16 hi/lo), per batch.
__device__ __nv_bfloat16 g_KCH[(size_t)M_ROWS * H_DIM];
__device__ __nv_bfloat16 g_KCL[(size_t)M_ROWS * H_DIM];
// Compacted V, TRANSPOSED per batch: [b][d][j], bf16 hi/lo; zero beyond nb.
__device__ __nv_bfloat16 g_VTH[(size_t)B_SZ * H_DIM * S_LEN];
__device__ __nv_bfloat16 g_VTL[(size_t)B_SZ * H_DIM * S_LEN];
// Q in bf16 hi/lo (for HMMA scores) — written by proj epilogue (z==0).
__device__ __nv_bfloat16 g_QH2[(size_t)M_ROWS * H_DIM];
__device__ __nv_bfloat16 g_QL2[(size_t)M_ROWS * H_DIM];
__device__ int g_nb[B_SZ];
__device__ int g_idx[B_SZ][S_LEN];    // compacted j -> dense index
__device__ int g_rank[B_SZ][S_LEN];   // dense n -> # unmasked before n

// Pre-converted bf16 hi/lo operands for the HMMA projection GEMMs.
__device__ __nv_bfloat16 g_XH[3][(size_t)M_ROWS * H_DIM];
__device__ __nv_bfloat16 g_XL[3][(size_t)M_ROWS * H_DIM];
__device__ __nv_bfloat16 g_WH[3][(size_t)H_DIM * H_DIM];
__device__ __nv_bfloat16 g_WL[3][(size_t)H_DIM * H_DIM];

// ---------------------------------------------------------------------------
// Helpers
// ---------------------------------------------------------------------------
__device__ __forceinline__ uint32_t smem_to_u32(const void* p) {
    uint32_t a;
    asm("{ .reg .u64 t; cvta.to.shared.u64 t, %1; cvt.u32.u64 %0, t; }"
        : "=r"(a) : "l"(p));
    return a;
}

__device__ __forceinline__ void mma16816(float* c, const uint32_t* a, const uint32_t* b)
{
    asm volatile(
        "mma.sync.aligned.m16n8k16.row.col.f32.bf16.bf16.f32 "
        "{%0,%1,%2,%3},{%4,%5,%6,%7},{%8,%9},{%0,%1,%2,%3};"
        : "+f"(c[0]), "+f"(c[1]), "+f"(c[2]), "+f"(c[3])
        : "r"(a[0]), "r"(a[1]), "r"(a[2]), "r"(a[3]), "r"(b[0]), "r"(b[1]));
}

__device__ __forceinline__ void ldsm4(uint32_t* r, uint32_t addr)
{
    asm volatile("ldmatrix.sync.aligned.m8n8.x4.shared.b16 {%0,%1,%2,%3},[%4];"
                 : "=r"(r[0]), "=r"(r[1]), "=r"(r[2]), "=r"(r[3]) : "r"(addr));
}

__device__ __forceinline__ void cvt4_split(
    float4 v, uint32_t& h0, uint32_t& h1, uint32_t& l0, uint32_t& l1)
{
    __nv_bfloat16 hx = __float2bfloat16_rn(v.x);
    __nv_bfloat16 hy = __float2bfloat16_rn(v.y);
    __nv_bfloat16 hz = __float2bfloat16_rn(v.z);
    __nv_bfloat16 hw = __float2bfloat16_rn(v.w);
    h0 = (uint32_t)__bfloat16_as_ushort(hx) | ((uint32_t)__bfloat16_as_ushort(hy) << 16);
    h1 = (uint32_t)__bfloat16_as_ushort(hz) | ((uint32_t)__bfloat16_as_ushort(hw) << 16);
    __nv_bfloat16 lx = __float2bfloat16_rn(v.x - __bfloat162float(hx));
    __nv_bfloat16 ly = __float2bfloat16_rn(v.y - __bfloat162float(hy));
    __nv_bfloat16 lz = __float2bfloat16_rn(v.z - __bfloat162float(hz));
    __nv_bfloat16 lw = __float2bfloat16_rn(v.w - __bfloat162float(hw));
    l0 = (uint32_t)__bfloat16_as_ushort(lx) | ((uint32_t)__bfloat16_as_ushort(ly) << 16);
    l1 = (uint32_t)__bfloat16_as_ushort(lz) | ((uint32_t)__bfloat16_as_ushort(lw) << 16);
}

__device__ __forceinline__ void cvt2_split(float2 v, uint32_t& h, uint32_t& l)
{
    __nv_bfloat16 hx = __float2bfloat16_rn(v.x);
    __nv_bfloat16 hy = __float2bfloat16_rn(v.y);
    h = (uint32_t)__bfloat16_as_ushort(hx) | ((uint32_t)__bfloat16_as_ushort(hy) << 16);
    __nv_bfloat16 lx = __float2bfloat16_rn(v.x - __bfloat162float(hx));
    __nv_bfloat16 ly = __float2bfloat16_rn(v.y - __bfloat162float(hy));
    l = (uint32_t)__bfloat16_as_ushort(lx) | ((uint32_t)__bfloat16_as_ushort(ly) << 16);
}

// ---------------------------------------------------------------------------
// Pre-convert X (seq-first fp32) and W to bf16 hi/lo (R13, proven).
// ---------------------------------------------------------------------------
__global__ __launch_bounds__(256) void preconv_kernel(
    const float* __restrict__ Xq, const float* __restrict__ Xk,
    const float* __restrict__ Xv,
    const float* __restrict__ Wq, const float* __restrict__ Wk,
    const float* __restrict__ Wv)
{
    const int row = blockIdx.x;          // 0..27647
    const int z = row / 9216;
    const int r = row % 9216;
    const int col = threadIdx.x * 4;

    const float* src;
    __nv_bfloat16 *dh, *dl;
    if (r < M_ROWS) {
        const float* X = (z == 0) ? Xq : ((z == 1) ? Xk : Xv);
        const int b = r >> 10, s = r & 1023;
        src = X + ((size_t)(s * B_SZ + b)) * H_DIM;
        dh = g_XH[z] + (size_t)r * H_DIM;
        dl = g_XL[z] + (size_t)r * H_DIM;
    } else {
        const int rw = r - M_ROWS;
        const float* W = (z == 0) ? Wq : ((z == 1) ? Wk : Wv);
        src = W + (size_t)rw * H_DIM;
        dh = g_WH[z] + (size_t)rw * H_DIM;
        dl = g_WL[z] + (size_t)rw * H_DIM;
    }

    float4 v = *reinterpret_cast<const float4*>(src + col);
    uint32_t h0, h1, l0, l1;
    cvt4_split(v, h0, h1, l0, l1);
    *reinterpret_cast<uint2*>(dh + col) = make_uint2(h0, h1);
    *reinterpret_cast<uint2*>(dl + col) = make_uint2(l0, l1);
}

// ---------------------------------------------------------------------------
// Projection GEMM via mma.sync (R13, proven) + z==0 writes Q bf16 hi/lo.
// ---------------------------------------------------------------------------
#define PROW 40   // padded row stride in bf16 elems (80B)

__global__ __launch_bounds__(256) void proj_mma_kernel(
    const float* __restrict__ bq, const float* __restrict__ bk,
    const float* __restrict__ bv)
{
    __shared__ __align__(16) uint16_t sAhi[128 * PROW];
    __shared__ __align__(16) uint16_t sAlo[128 * PROW];
    __shared__ __align__(16) uint16_t sBhi[128 * PROW];
    __shared__ __align__(16) uint16_t sBlo[128 * PROW];

    const int z = blockIdx.z;
    const float* bias = (z == 0) ? bq : ((z == 1) ? bk : bv);
    float* out        = (z == 0) ? g_QL : ((z == 1) ? g_KL : g_VL);

    const int m0 = blockIdx.y * 128;
    const int n0 = blockIdx.x * 128;

    const __nv_bfloat16* Ah = g_XH[z] + (size_t)m0 * H_DIM;
    const __nv_bfloat16* Al = g_XL[z] + (size_t)m0 * H_DIM;
    const __nv_bfloat16* Bh = g_WH[z] + (size_t)n0 * H_DIM;
    const __nv_bfloat16* Bl = g_WL[z] + (size_t)n0 * H_DIM;

    const int tid  = threadIdx.x;
    const int lane = tid & 31;
    const int wid  = tid >> 5;
    const int warp_m = wid & 1;
    const int warp_n = wid >> 1;

    const uint32_t uAhi = smem_to_u32(sAhi);
    const uint32_t uAlo = smem_to_u32(sAlo);
    const uint32_t uBhi = smem_to_u32(sBhi);
    const uint32_t uBlo = smem_to_u32(sBlo);

    float acc[4][4][4];
    #pragma unroll
    for (int i = 0; i < 4; i++)
        #pragma unroll
        for (int j = 0; j < 4; j++)
            #pragma unroll
            for (int k = 0; k < 4; k++) acc[i][j][k] = 0.0f;

    const int sr = tid >> 1;
    const int hf = tid & 1;

    const int a_row = warp_m * 64 + (lane & 15);
    const uint32_t a_colb = (uint32_t)((lane >> 4) << 4);
    const int b_row = warp_n * 32 + (lane & 7) + ((lane & 16) ? 8 : 0);
    const uint32_t b_colb = (uint32_t)((lane & 8) ? 16 : 0);

    for (int c = 0; c < H_DIM / 32; c++) {
        {
            const size_t go = (size_t)sr * H_DIM + c * 32 + hf * 16;
            const int    so = sr * PROW + hf * 16;
            #pragma unroll
            for (int i = 0; i < 4; i++) {
                *reinterpret_cast<uint2*>(&sAhi[so + i * 4]) =
                    *reinterpret_cast<const uint2*>(Ah + go + i * 4);
                *reinterpret_cast<uint2*>(&sAlo[so + i * 4]) =
                    *reinterpret_cast<const uint2*>(Al + go + i * 4);
                *reinterpret_cast<uint2*>(&sBhi[so + i * 4]) =
                    *reinterpret_cast<const uint2*>(Bh + go + i * 4);
                *reinterpret_cast<uint2*>(&sBlo[so + i * 4]) =
                    *reinterpret_cast<const uint2*>(Bl + go + i * 4);
            }
        }
        __syncthreads();

        #pragma unroll
        for (int ks = 0; ks < 2; ks++) {
            const uint32_t kb = (uint32_t)(ks * 32);
            uint32_t ahi[4][4], alo[4][4], bhi[4][2], blo[4][2];
            #pragma unroll
            for (int mt = 0; mt < 4; mt++) {
                uint32_t off = (uint32_t)((a_row + mt * 16) * (PROW * 2)) + kb + a_colb;
                ldsm4(ahi[mt], uAhi + off);
                ldsm4(alo[mt], uAlo + off);
            }
            {
                uint32_t t[4];
                uint32_t off0 = (uint32_t)(b_row * (PROW * 2)) + kb + b_colb;
                uint32_t off1 = (uint32_t)((b_row + 16) * (PROW * 2)) + kb + b_colb;
                ldsm4(t, uBhi + off0);
                bhi[0][0] = t[0]; bhi[0][1] = t[1]; bhi[1][0] = t[2]; bhi[1][1] = t[3];
                ldsm4(t, uBhi + off1);
                bhi[2][0] = t[0]; bhi[2][1] = t[1]; bhi[3][0] = t[2]; bhi[3][1] = t[3];
                ldsm4(t, uBlo + off0);
                blo[0][0] = t[0]; blo[0][1] = t[1]; blo[1][0] = t[2]; blo[1][1] = t[3];
                ldsm4(t, uBlo + off1);
                blo[2][0] = t[0]; blo[2][1] = t[1]; blo[3][0] = t[2]; blo[3][1] = t[3];
            }
            #pragma unroll
            for (int mt = 0; mt < 4; mt++)
                #pragma unroll
                for (int nt = 0; nt < 4; nt++) {
                    mma16816(acc[mt][nt], ahi[mt], bhi[nt]);
                    mma16816(acc[mt][nt], ahi[mt], blo[nt]);
                    mma16816(acc[mt][nt], alo[mt], bhi[nt]);
                }
        }
        __syncthreads();
    }

    const int g  = lane >> 2;
    const int tg = lane & 3;
    #pragma unroll
    for (int nt = 0; nt < 4; nt++) {
        const int ncol = n0 + warp_n * 32 + nt * 8 + tg * 2;
        const float2 bv2 = *reinterpret_cast<const float2*>(bias + ncol);
        #pragma unroll
        for (int mt = 0; mt < 4; mt++) {
            const int m = m0 + warp_m * 64 + mt * 16 + g;
            float2 o0 = make_float2(acc[mt][nt][0] + bv2.x, acc[mt][nt][1] + bv2.y);
            float2 o1 = make_float2(acc[mt][nt][2] + bv2.x, acc[mt][nt][3] + bv2.y);
            *reinterpret_cast<float2*>(out + (size_t)m * H_DIM + ncol)       = o0;
            *reinterpret_cast<float2*>(out + (size_t)(m + 8) * H_DIM + ncol) = o1;
            if (z == 0) {
                uint32_t h, l;
                cvt2_split(o0, h, l);
                *reinterpret_cast<uint32_t*>(&g_QH2[(size_t)m * H_DIM + ncol]) = h;
                *reinterpret_cast<uint32_t*>(&g_QL2[(size_t)m * H_DIM + ncol]) = l;
                cvt2_split(o1, h, l);
                *reinterpret_cast<uint32_t*>(&g_QH2[(size_t)(m + 8) * H_DIM + ncol]) = h;
                *reinterpret_cast<uint32_t*>(&g_QL2[(size_t)(m + 8) * H_DIM + ncol]) = l;
            }
        }
    }
}

// ---------------------------------------------------------------------------
// Mask compaction (R12, proven).
// ---------------------------------------------------------------------------
__global__ void compact_kernel(const int* __restrict__ mask)
{
    const int b = blockIdx.x;
    const int tid = threadIdx.x;
    const int lane = tid & 31, wid = tid >> 5;

    int um = (mask[b * S_LEN + tid] == 0) ? 1 : 0;
    unsigned bal = __ballot_sync(0xffffffffu, um);
    int pre = __popc(bal & ((1u << lane) - 1));
    int wcnt = __popc(bal);

    __shared__ int wbase[32];
    __shared__ int wpre[32];
    if (lane == 0) wbase[wid] = wcnt;
    __syncthreads();
    if (wid == 0) {
        int v = wbase[lane];
        int x = v;
        #pragma unroll
        for (int o = 1; o < 32; o <<= 1) {
            int y = __shfl_up_sync(0xffffffffu, x, o);
            if (lane >= o) x += y;
        }
        wpre[lane] = x - v;
        if (lane == 31) g_nb[b] = x;
    }
    __syncthreads();

    int r = wpre[wid] + pre;
    g_rank[b][tid] = r;
    if (um) g_idx[b][r] = tid;
}

// ---------------------------------------------------------------------------
// Gather compacted K rows as bf16 hi/lo. grid (S_LEN, B_SZ), block 256.
// ---------------------------------------------------------------------------
__global__ void gather_kernel()
{
    const int b = blockIdx.y;
    const int j = blockIdx.x;
    if (j >= g_nb[b]) return;
    const int src = g_idx[b][j];
    const size_t so = ((size_t)b * S_LEN + src) * H_DIM;
    const size_t dof = ((size_t)b * S_LEN + j) * H_DIM;
    const int c = threadIdx.x * 4;

    float4 kv = *reinterpret_cast<const float4*>(g_KL + so + c);
    uint32_t h0, h1, l0, l1;
    cvt4_split(kv, h0, h1, l0, l1);
    *reinterpret_cast<uint2*>(g_KCH + dof + c) = make_uint2(h0, h1);
    *reinterpret_cast<uint2*>(g_KCL + dof + c) = make_uint2(l0, l1);
}

// ---------------------------------------------------------------------------
// Gather + TRANSPOSE compacted V to [b][d][j] bf16 hi/lo (R16, proven).
// ---------------------------------------------------------------------------
__global__ __launch_bounds__(256) void vtrans_kernel()
{
    const int jt = blockIdx.x;
    const int dt = blockIdx.y;
    const int b  = blockIdx.z;
    const int nb = g_nb[b];
    if (jt * 32 >= nb) return;

    __shared__ uint16_t sh[32][36];
    __shared__ uint16_t sl[32][36];

    const int tid = threadIdx.x;
    const int jl = tid >> 3;
    const int c4 = (tid & 7) * 4;

    const int j = jt * 32 + jl;
    float4 v = make_float4(0.f, 0.f, 0.f, 0.f);
    if (j < nb) {
        const int src = g_idx[b][j];
        v = *reinterpret_cast<const float4*>(
            g_VL + ((size_t)(b * S_LEN + src)) * H_DIM + dt * 32 + c4);
    }
    uint32_t h0, h1, l0, l1;
    cvt4_split(v, h0, h1, l0, l1);
    *reinterpret_cast<uint2*>(&sh[jl][c4]) = make_uint2(h0, h1);
    *reinterpret_cast<uint2*>(&sl[jl][c4]) = make_uint2(l0, l1);
    __syncthreads();

    const int dl = tid >> 3;
    const int jc4 = (tid & 7) * 4;
    uint32_t w0 = (uint32_t)sh[jc4 + 0][dl] | ((uint32_t)sh[jc4 + 1][dl] << 16);
    uint32_t w1 = (uint32_t)sh[jc4 + 2][dl] | ((uint32_t)sh[jc4 + 3][dl] << 16);
    const size_t dof = ((size_t)(b * H_DIM + dt * 32 + dl)) * S_LEN + jt * 32 + jc4;
    *reinterpret_cast<uint2*>(g_VTH + dof) = make_uint2(w0, w1);
    w0 = (uint32_t)sl[jc4 + 0][dl] | ((uint32_t)sl[jc4 + 1][dl] << 16);
    w1 = (uint32_t)sl[jc4 + 2][dl] | ((uint32_t)sl[jc4 + 3][dl] << 16);
    *reinterpret_cast<uint2*>(g_VTL + dof) = make_uint2(w0, w1);
}

// ---------------------------------------------------------------------------
// Fused flash-style attention over COMPACTED keys (phase 2 ELIMINATED):
//   Per ktile: stage K -> S-mma -> (K buffer freed) stage V^T into the SAME
//   buffer; meanwhile (regs only): store raw scores to W once, online-max
//   update with ctx-accumulator rescale, P := exp(s-m) in place; then PV via
//   3-term HMMA with A-fragments built DIRECTLY from the P registers (score
//   C-fragment layout == A-fragment layout). Ctx normalized by 1/l at the
//   epilogue. Phase 3 normalizes raw W during expansion (exp(v-m)*il).
// ---------------------------------------------------------------------------
#define SM_QH 0
#define SM_QL 18432
#define SM_KH 36864          // K tile hi; V^T hi aliases here after S-mma
#define SM_KL 55296          // K tile lo
#define SM_VH 36864          // V^T hi (64 x 136 bf16)
#define SM_VL 54272          // V^T lo
#define SM_BUF 0
#define SM_RANK 16896
#define SM_UM 20992
#define SM_MOFF 73728
#define SM_ILOFF 74240
#define ATTN_SMEM 74752
#define QKROW 72   // Q/K row stride in bf16 elems (144B)
#define VROW 136   // V^T row stride in bf16 elems (272B)

__global__ __launch_bounds__(256, 2) void attn_kernel(
    const int* __restrict__ mask, float* w, float* out_ctx)
{
    extern __shared__ char smx[];
    float* sm_m  = reinterpret_cast<float*>(smx + SM_MOFF);
    float* sm_il = reinterpret_cast<float*>(smx + SM_ILOFF);

    const int bh = blockIdx.y;
    const int b = bh >> 4;
    const int h = bh & 15;
    const int q0 = blockIdx.x * 128;
    float* W = w + (size_t)bh * S_LEN * S_LEN;

    const int tid = threadIdx.x;
    const int lane = tid & 31;
    const int wp  = tid >> 5;
    const int g   = lane >> 2;
    const int tg  = lane & 3;

    const int nb = g_nb[b];
    const int ktiles = (nb + 127) >> 7;

    // ============ Phase 1+2 fused: scores + online softmax + PV ===========
    {
        uint16_t* sQh = reinterpret_cast<uint16_t*>(smx + SM_QH);
        uint16_t* sQl = reinterpret_cast<uint16_t*>(smx + SM_QL);
        uint16_t* sKh = reinterpret_cast<uint16_t*>(smx + SM_KH);
        uint16_t* sKl = reinterpret_cast<uint16_t*>(smx + SM_KL);
        uint16_t* sVh = reinterpret_cast<uint16_t*>(smx + SM_VH);
        uint16_t* sVl = reinterpret_cast<uint16_t*>(smx + SM_VL);
        const uint32_t uQh = smem_to_u32(sQh);
        const uint32_t uQl = smem_to_u32(sQl);
        const uint32_t uKh = smem_to_u32(sKh);
        const uint32_t uKl = smem_to_u32(sKl);
        const uint32_t uVh = smem_to_u32(sVh);
        const uint32_t uVl = smem_to_u32(sVl);

        const __nv_bfloat16* VTh = g_VTH + ((size_t)(b * H_DIM + h * HDIM)) * S_LEN;
        const __nv_bfloat16* VTl = g_VTL + ((size_t)(b * H_DIM + h * HDIM)) * S_LEN;

        // stage Q tile once (R15-proven pattern)
        {
            const int row = tid >> 1, hf = tid & 1;
            const size_t go = ((size_t)(b * S_LEN + q0 + row)) * H_DIM + h * HDIM + hf * 32;
            const int so = row * QKROW + hf * 32;
            #pragma unroll
            for (int i = 0; i < 4; i++) {
                *reinterpret_cast<uint4*>(&sQh[so + i * 8]) =
                    *reinterpret_cast<const uint4*>(g_QH2 + go + i * 8);
                *reinterpret_cast<uint4*>(&sQl[so + i * 8]) =
                    *reinterpret_cast<const uint4*>(g_QL2 + go + i * 8);
            }
        }

        float row_m0 = -CUDART_INF_F, row_l0 = 0.0f;
        float row_m1 = -CUDART_INF_F, row_l1 = 0.0f;

        float cacc[8][4];
        #pragma unroll
        for (int nt = 0; nt < 8; nt++)
            #pragma unroll
            for (int q = 0; q < 4; q++) cacc[nt][q] = 0.0f;

        const uint32_t a_base = (uint32_t)((wp * 16 + (lane & 15)) * (QKROW * 2))
                              + (uint32_t)((lane >> 4) << 4);
        const uint32_t b_rowsel = (uint32_t)(((lane & 7) + ((lane & 16) ? 8 : 0)) * (QKROW * 2))
                                + (uint32_t)((lane & 8) ? 16 : 0);
        const uint32_t vb_rowsel = (uint32_t)(((lane & 7) + ((lane & 16) ? 8 : 0)) * (VROW * 2))
                                 + (uint32_t)((lane & 8) ? 16 : 0);

        for (int kt = 0; kt < ktiles; kt++) {
            // ---- stage K tile (R15-proven) ----
            {
                const int row = tid >> 1, hf = tid & 1;
                const size_t go = ((size_t)(b * S_LEN + kt * 128 + row)) * H_DIM
                                + h * HDIM + hf * 32;
                const int so = row * QKROW + hf * 32;
                #pragma unroll
                for (int i = 0; i < 4; i++) {
                    *reinterpret_cast<uint4*>(&sKh[so + i * 8]) =
                        *reinterpret_cast<const uint4*>(g_KCH + go + i * 8);
                    *reinterpret_cast<uint4*>(&sKl[so + i * 8]) =
                        *reinterpret_cast<const uint4*>(g_KCL + go + i * 8);
                }
            }
            __syncthreads();

            // ---- S = Q K^T (3-term HMMA, R15-proven) ----
            float acc[16][4];
            #pragma unroll
            for (int nt = 0; nt < 16; nt++)
                #pragma unroll
                for (int q = 0; q < 4; q++) acc[nt][q] = 0.0f;

            #pragma unroll
            for (int ks = 0; ks < 4; ks++) {
                const uint32_t kb = (uint32_t)(ks * 32);
                uint32_t ah[4], al[4];
                ldsm4(ah, uQh + a_base + kb);
                ldsm4(al, uQl + a_base + kb);
                #pragma unroll
                for (int p = 0; p < 8; p++) {
                    uint32_t koff = (uint32_t)(p * 16 * (QKROW * 2)) + b_rowsel + kb;
                    uint32_t bh4[4], bl4[4];
                    ldsm4(bh4, uKh + koff);
                    ldsm4(bl4, uKl + koff);
                    mma16816(acc[2 * p],     ah, bh4);
                    mma16816(acc[2 * p],     ah, bl4);
                    mma16816(acc[2 * p],     al, bh4);
                    mma16816(acc[2 * p + 1], ah, bh4 + 2);
                    mma16816(acc[2 * p + 1], ah, bl4 + 2);
                    mma16816(acc[2 * p + 1], al, bh4 + 2);
                }
            }
            __syncthreads();   // K buffer now free

            // ---- stage V^T tile into the freed K buffer ----
            {
                const int r = tid >> 2;          // 0..63 (d row)
                const int q4 = tid & 3;          // 32 j-cols each
                const size_t go = (size_t)r * S_LEN + kt * 128 + q4 * 32;
                const int so = r * VROW + q4 * 32;
                #pragma unroll
                for (int i = 0; i < 4; i++) {
                    *reinterpret_cast<uint4*>(&sVh[so + i * 8]) =
                        *reinterpret_cast<const uint4*>(VTh + go + i * 8);
                    *reinterpret_cast<uint4*>(&sVl[so + i * 8]) =
                        *reinterpret_cast<const uint4*>(VTl + go + i * 8);
                }
            }

            // ---- register-only: scale+mask, raw W store, stats, P ----
            #pragma unroll
            for (int nt = 0; nt < 16; nt++) {
                const int c0 = kt * 128 + nt * 8 + tg * 2;
                const float m0 = (c0     < nb) ? 0.0f : -1000000.0f;
                const float m1 = (c0 + 1 < nb) ? 0.0f : -1000000.0f;
                acc[nt][0] = acc[nt][0] * 0.125f + m0;
                acc[nt][1] = acc[nt][1] * 0.125f + m1;
                acc[nt][2] = acc[nt][2] * 0.125f + m0;
                acc[nt][3] = acc[nt][3] * 0.125f + m1;
            }

            // raw score store (before exp overwrites acc)
            {
                float* wr0 = W + (size_t)(q0 + wp * 16 + g) * S_LEN + kt * 128 + tg * 2;
                float* wr1 = wr0 + (size_t)8 * S_LEN;
                #pragma unroll
                for (int nt = 0; nt < 16; nt++) {
                    *reinterpret_cast<float2*>(wr0 + nt * 8) = make_float2(acc[nt][0], acc[nt][1]);
                    *reinterpret_cast<float2*>(wr1 + nt * 8) = make_float2(acc[nt][2], acc[nt][3]);
                }
            }

            float tm0 = -CUDART_INF_F, tm1 = -CUDART_INF_F;
            #pragma unroll
            for (int nt = 0; nt < 16; nt++) {
                tm0 = fmaxf(tm0, fmaxf(acc[nt][0], acc[nt][1]));
                tm1 = fmaxf(tm1, fmaxf(acc[nt][2], acc[nt][3]));
            }
            tm0 = fmaxf(tm0, __shfl_xor_sync(0xffffffffu, tm0, 1));
            tm0 = fmaxf(tm0, __shfl_xor_sync(0xffffffffu, tm0, 2));
            tm1 = fmaxf(tm1, __shfl_xor_sync(0xffffffffu, tm1, 1));
            tm1 = fmaxf(tm1, __shfl_xor_sync(0xffffffffu, tm1, 2));

            const float mn0 = fmaxf(row_m0, tm0);
            const float mn1 = fmaxf(row_m1, tm1);
            const float sc0 = __expf(row_m0 - mn0);   // 0 on first tile (m=-inf)
            const float sc1 = __expf(row_m1 - mn1);
            row_m0 = mn0;
            row_m1 = mn1;

            // rescale ctx accumulators
            #pragma unroll
            for (int nt = 0; nt < 8; nt++) {
                cacc[nt][0] *= sc0; cacc[nt][1] *= sc0;
                cacc[nt][2] *= sc1; cacc[nt][3] *= sc1;
            }

            // P := exp(s - m) in place; row sums
            float ts0 = 0.0f, ts1 = 0.0f;
            #pragma unroll
            for (int nt = 0; nt < 16; nt++) {
                acc[nt][0] = __expf(acc[nt][0] - mn0);
                acc[nt][1] = __expf(acc[nt][1] - mn0);
                acc[nt][2] = __expf(acc[nt][2] - mn1);
                acc[nt][3] = __expf(acc[nt][3] - mn1);
                ts0 += acc[nt][0] + acc[nt][1];
                ts1 += acc[nt][2] + acc[nt][3];
            }
            ts0 += __shfl_xor_sync(0xffffffffu, ts0, 1);
            ts0 += __shfl_xor_sync(0xffffffffu, ts0, 2);
            ts1 += __shfl_xor_sync(0xffffffffu, ts1, 1);
            ts1 += __shfl_xor_sync(0xffffffffu, ts1, 2);
            row_l0 = row_l0 * sc0 + ts0;
            row_l1 = row_l1 * sc1 + ts1;

            __syncthreads();   // V^T tile visible

            // ---- PV: A-fragments from P registers, 3-term HMMA ----
            #pragma unroll
            for (int ks = 0; ks < 8; ks++) {
                uint32_t ph[4], pl[4];
                cvt2_split(make_float2(acc[2 * ks][0],     acc[2 * ks][1]),     ph[0], pl[0]);
                cvt2_split(make_float2(acc[2 * ks][2],     acc[2 * ks][3]),     ph[1], pl[1]);
                cvt2_split(make_float2(acc[2 * ks + 1][0], acc[2 * ks + 1][1]), ph[2], pl[2]);
                cvt2_split(make_float2(acc[2 * ks + 1][2], acc[2 * ks + 1][3]), ph[3], pl[3]);
                const uint32_t kb = (uint32_t)(ks * 32);
                #pragma unroll
                for (int p = 0; p < 4; p++) {
                    uint32_t koff = (uint32_t)(p * 16 * (VROW * 2)) + vb_rowsel + kb;
                    uint32_t vh4[4], vl4[4];
                    ldsm4(vh4, uVh + koff);
                    ldsm4(vl4, uVl + koff);
                    mma16816(cacc[2 * p],     ph, vh4);
                    mma16816(cacc[2 * p],     ph, vl4);
                    mma16816(cacc[2 * p],     pl, vh4);
                    mma16816(cacc[2 * p + 1], ph, vh4 + 2);
                    mma16816(cacc[2 * p + 1], ph, vl4 + 2);
                    mma16816(cacc[2 * p + 1], pl, vh4 + 2);
                }
            }
            __syncthreads();   // V buffer free for next K stage
        }

        // stats for phase 3
        if (tg == 0) {
            sm_m[wp * 16 + g]      = row_m0;
            sm_il[wp * 16 + g]     = 1.0f / row_l0;
            sm_m[wp * 16 + g + 8]  = row_m1;
            sm_il[wp * 16 + g + 8] = 1.0f / row_l1;
        }

        // ctx epilogue (normalize by 1/l)
        const float il0 = 1.0f / row_l0;
        const float il1 = 1.0f / row_l1;
        const int s0 = q0 + wp * 16 + g;
        #pragma unroll
        for (int nt = 0; nt < 8; nt++) {
            const int d = nt * 8 + tg * 2;
            *reinterpret_cast<float2*>(
                out_ctx + ((size_t)s0 * B_SZ + b) * H_DIM + h * HDIM + d) =
                make_float2(cacc[nt][0] * il0, cacc[nt][1] * il0);
            *reinterpret_cast<float2*>(
                out_ctx + ((size_t)(s0 + 8) * B_SZ + b) * H_DIM + h * HDIM + d) =
                make_float2(cacc[nt][2] * il1, cacc[nt][3] * il1);
        }
    }
    __syncthreads();

    // ====== Phase 3: normalize + expand compacted -> dense weights ========
    {
        float (*smbuf)[33] = reinterpret_cast<float(*)[33]>(smx + SM_BUF);
        int* sm_rank = reinterpret_cast<int*>(smx + SM_RANK);
        int* sm_um   = reinterpret_cast<int*>(smx + SM_UM);

        for (int n = tid; n < S_LEN; n += 256) {
            sm_rank[n] = g_rank[b][n];
            sm_um[n]   = (mask[b * S_LEN + n] == 0) ? 1 : 0;
        }
        __syncthreads();

        const int row  = tid >> 1;
        const int half = tid & 1;
        float* wrow = W + (size_t)(q0 + row) * S_LEN;
        const float mm = sm_m[row];
        const float il = sm_il[row];

        for (int s = 31; s >= 0; s--) {
            const int n0 = s * 32;
            const int r0 = sm_rank[n0];
            const int r1 = (n0 + 32 < S_LEN) ? sm_rank[n0 + 32] : nb;
            const int width = r1 - r0;

            // buffer this segment's normalized weights (raw -> softmax)
            for (int i = half; i < width; i += 2)
                smbuf[row][i] = __expf(wrow[r0 + i] - mm) * il;
            __syncthreads();

            #pragma unroll
            for (int i = 0; i < 4; i++) {
                const int nb4 = n0 + half * 16 + i * 4;
                float4 o;
                o.x = sm_um[nb4 + 0] ? smbuf[row][sm_rank[nb4 + 0] - r0] : 0.0f;
                o.y = sm_um[nb4 + 1] ? smbuf[row][sm_rank[nb4 + 1] - r0] : 0.0f;
                o.z = sm_um[nb4 + 2] ? smbuf[row][sm_rank[nb4 + 2] - r0] : 0.0f;
                o.w = sm_um[nb4 + 3] ? smbuf[row][sm_rank[nb4 + 3] - r0] : 0.0f;
                *reinterpret_cast<float4*>(wrow + nb4) = o;
            }
            __syncthreads();
        }
    }
}

// ---------------------------------------------------------------------------
// Launch
// ---------------------------------------------------------------------------
extern "C" void kernel_launch(void* const* d_in, const int* in_sizes, int n_in,
                              void* d_out, int out_size)
{
    const float* q_states = (const float*)d_in[0];
    const float* k_states = (const float*)d_in[1];
    const float* v_states = (const float*)d_in[2];
    const int*   mask     = (const int*)  d_in[3];
    const float* Wq = (const float*)d_in[4];
    const float* bq = (const float*)d_in[5];
    const float* Wk = (const float*)d_in[6];
    const float* bk = (const float*)d_in[7];
    const float* Wv = (const float*)d_in[8];
    const float* bv = (const float*)d_in[9];

    float* out_ctx = (float*)d_out;                           // [S, B, H]
    float* out_w   = out_ctx + (size_t)S_LEN * B_SZ * H_DIM;  // [B, NH, S, S]

    static int smem_set = 0;
    if (!smem_set) {
        cudaFuncSetAttribute(attn_kernel,
                             cudaFuncAttributeMaxDynamicSharedMemorySize,
                             ATTN_SMEM);
        smem_set = 1;
    }

    preconv_kernel<<<3 * (M_ROWS + H_DIM), 256>>>(
        q_states, k_states, v_states, Wq, Wk, Wv);

    dim3 pg(H_DIM / 128, M_ROWS / 128, 3);   // (8, 64, 3)
    proj_mma_kernel<<<pg, 256>>>(bq, bk, bv);

    compact_kernel<<<B_SZ, 1024>>>(mask);
    gather_kernel<<<dim3(S_LEN, B_SZ), 256>>>();
    vtrans_kernel<<<dim3(32, 32, B_SZ), 256>>>();

    dim3 ag(S_LEN / 128, B_SZ * NHEAD);      // (8, 128)
    attn_kernel<<<ag, 256, ATTN_SMEM>>>(mask, out_w, out_ctx);
}